// round 11
// baseline (speedup 1.0000x reference)
#include <cuda_runtime.h>

// Problem constants
#define B_ 8
#define N_ 2048
#define F_ 128
#define M_ (B_*N_)          // 16384 total rows
#define LAYERS_ 2
#define NSPLIT_ 16
#define SLOPE_ 0.1f
#define INV_NM1_ (1.0f/2047.0f)
#define PADT_ 68            // XsT row pad for 64 rows: 68*4 = 272 bytes, multiple of 16
#define PADS_ 68            // As pad in calc_S (64 cols + pad)
#define NT_ 256             // threads per block, 2 CTAs/SM

typedef unsigned long long ull;

// Scratch (device globals; no cudaMalloc allowed)
__device__ float g_w1[M_*F_];
__device__ float g_w2[M_*F_];
__device__ float g_diag[M_];
__device__ float g_Spart[B_*NSPLIT_*F_*F_];
__device__ float g_S[B_*F_*F_];

__device__ __forceinline__ float lrelu(float v) { return v >= 0.f ? v : SLOPE_*v; }

// ---- packed fp32x2 helpers (sm_100+: one FFMA2 issue = 2 FMAs) ----
__device__ __forceinline__ ull dup2(float a) {
    ull r; asm("mov.b64 %0, {%1, %1};" : "=l"(r) : "f"(a)); return r;
}
__device__ __forceinline__ ull ffma2(ull a, ull b, ull c) {
    ull d; asm("fma.rn.f32x2 %0, %1, %2, %3;" : "=l"(d) : "l"(a), "l"(b), "l"(c));
    return d;
}
__device__ __forceinline__ float2 unpk(ull v) {
    float2 f; asm("mov.b64 {%0, %1}, %2;" : "=f"(f.x), "=f"(f.y) : "l"(v)); return f;
}

// ---------------------------------------------------------------------------
// 256 threads: tx = tid&31 (4 cols -> 128), ty = tid>>5 (0..7 -> 64 rows).
// A transposed in smem: XsT[k][row] (64 rows). Row-pair packed accumulators:
// acc2[p][j] holds rows {ty*8+2p, ty*8+2p+1} of col tx*4+j.
// ---------------------------------------------------------------------------
__device__ __forceinline__ void load_XT_chunk(
    const float* __restrict__ X, int row0, int c, int tid, float (*XsT)[PADT_])
{
    #pragma unroll
    for (int i = 0; i < 2; ++i) {
        int f4 = tid + i*NT_;
        int r  = f4 >> 3;             // 0..63
        int kq = (f4 & 7) << 2;       // 0..28
        float4 v = *(const float4*)&X[(size_t)(row0 + r)*F_ + c*32 + kq];
        XsT[kq+0][r] = v.x; XsT[kq+1][r] = v.y;
        XsT[kq+2][r] = v.z; XsT[kq+3][r] = v.w;
    }
}

__device__ __forceinline__ void load_W_chunk(
    const float* __restrict__ W, int c, int tid, float (*Ws)[128])
{
    #pragma unroll
    for (int i = 0; i < 4; ++i) {
        int f4 = tid + i*NT_;
        int r  = f4 >> 5;
        int q  = (f4 & 31) << 2;
        *(float4*)&Ws[r][q] = *(const float4*)&W[(size_t)(c*32 + r)*F_ + q];
    }
}

__device__ __forceinline__ void load_a2(
    const float (*XsT)[PADT_], int k, int ty, ull a2[4])
{
    ulonglong2 t0 = *(const ulonglong2*)&XsT[k][ty*8];
    ulonglong2 t1 = *(const ulonglong2*)&XsT[k][ty*8 + 4];
    a2[0] = t0.x; a2[1] = t0.y; a2[2] = t1.x; a2[3] = t1.y;
}

__device__ __forceinline__ void mac_chunk(
    const float (*XsT)[PADT_], const float (*Ws)[128],
    int tx, int ty, ull acc2[4][4])
{
    #pragma unroll
    for (int k = 0; k < 32; ++k) {
        ull a2[4];
        load_a2(XsT, k, ty, a2);
        float4 bv = *(const float4*)&Ws[k][tx*4];
        ull b2[4] = { dup2(bv.x), dup2(bv.y), dup2(bv.z), dup2(bv.w) };
        #pragma unroll
        for (int p = 0; p < 4; ++p)
            #pragma unroll
            for (int j = 0; j < 4; ++j)
                acc2[p][j] = ffma2(a2[p], b2[j], acc2[p][j]);
    }
}

__device__ __forceinline__ void zero_acc(ull acc2[4][4]) {
    #pragma unroll
    for (int p = 0; p < 4; ++p)
        #pragma unroll
        for (int j = 0; j < 4; ++j) acc2[p][j] = 0ull;
}

// ---------------------------------------------------------------------------
// Fused single-pass: w1 = lrelu(x@W3+b3), w2 = lrelu(x@W4+b4), diag = w1.w2.
// 64-row tiles, 256 threads, 2 CTAs/SM.
// ---------------------------------------------------------------------------
__global__ void __launch_bounds__(NT_, 2) k_w1w2(
    const float* __restrict__ X,
    const float* __restrict__ W3, const float* __restrict__ b3,
    const float* __restrict__ W4, const float* __restrict__ b4,
    float* __restrict__ Y1, float* __restrict__ Y2, float* __restrict__ diag)
{
    __shared__ float XsT[32][PADT_];
    __shared__ float Ws3[32][128];
    __shared__ float Ws4[32][128];

    const int row0 = blockIdx.x * 64;
    const int tid  = threadIdx.x;
    const int tx   = tid & 31;
    const int ty   = tid >> 5;
    const int lane = tid & 31;

    ull acc3[4][4], acc4[4][4];
    zero_acc(acc3); zero_acc(acc4);

    for (int c = 0; c < 4; ++c) {
        load_XT_chunk(X, row0, c, tid, XsT);
        load_W_chunk(W3, c, tid, Ws3);
        load_W_chunk(W4, c, tid, Ws4);
        __syncthreads();
        #pragma unroll
        for (int k = 0; k < 32; ++k) {
            ull a2[4];
            load_a2(XsT, k, ty, a2);
            float4 bv3 = *(const float4*)&Ws3[k][tx*4];
            float4 bv4 = *(const float4*)&Ws4[k][tx*4];
            ull b3d[4] = { dup2(bv3.x), dup2(bv3.y), dup2(bv3.z), dup2(bv3.w) };
            ull b4d[4] = { dup2(bv4.x), dup2(bv4.y), dup2(bv4.z), dup2(bv4.w) };
            #pragma unroll
            for (int p = 0; p < 4; ++p) {
                #pragma unroll
                for (int j = 0; j < 4; ++j) {
                    acc3[p][j] = ffma2(a2[p], b3d[j], acc3[p][j]);
                    acc4[p][j] = ffma2(a2[p], b4d[j], acc4[p][j]);
                }
            }
        }
        __syncthreads();
    }

    float4 bb3 = *(const float4*)&b3[tx*4];
    float4 bb4 = *(const float4*)&b4[tx*4];
    #pragma unroll
    for (int p = 0; p < 4; ++p) {
        float w1a[2][4], w2a[2][4];
        #pragma unroll
        for (int j = 0; j < 4; ++j) {
            float2 f3 = unpk(acc3[p][j]);
            float2 f4v = unpk(acc4[p][j]);
            const float* pb3 = (const float*)&bb3;
            const float* pb4 = (const float*)&bb4;
            w1a[0][j] = lrelu(f3.x + pb3[j]);
            w1a[1][j] = lrelu(f3.y + pb3[j]);
            w2a[0][j] = lrelu(f4v.x + pb4[j]);
            w2a[1][j] = lrelu(f4v.y + pb4[j]);
        }
        #pragma unroll
        for (int h = 0; h < 2; ++h) {
            const size_t r = (size_t)(row0 + ty*8 + 2*p + h);
            *(float4*)&Y1[r*F_ + tx*4] = *(float4*)&w1a[h][0];
            *(float4*)&Y2[r*F_ + tx*4] = *(float4*)&w2a[h][0];
            float d = w1a[h][0]*w2a[h][0] + w1a[h][1]*w2a[h][1]
                    + w1a[h][2]*w2a[h][2] + w1a[h][3]*w2a[h][3];
            d += __shfl_xor_sync(0xffffffffu, d, 1);
            d += __shfl_xor_sync(0xffffffffu, d, 2);
            d += __shfl_xor_sync(0xffffffffu, d, 4);
            d += __shfl_xor_sync(0xffffffffu, d, 8);
            d += __shfl_xor_sync(0xffffffffu, d, 16);
            if (lane == 0) diag[r] = d;
        }
    }
}

// ---------------------------------------------------------------------------
// Split-K partials of S[b] = w2[b]^T @ x[b].
// grid = (NSPLIT_, B_, 2): z selects 64 output rows (= w2 columns m0..m0+63).
// ---------------------------------------------------------------------------
__global__ void __launch_bounds__(NT_, 2) calc_S(
    const float* __restrict__ w2, const float* __restrict__ x,
    float* __restrict__ Spart)
{
    const int split = blockIdx.x;
    const int b     = blockIdx.y;
    const int m0    = blockIdx.z * 64;     // output row block (w2 column offset)
    const int k0    = b*N_ + split*128;

    __shared__ float As[32][PADS_];   // w2 chunk [k][m-local]  (64 cols)
    __shared__ float Bs[32][128];     // x  chunk [k][n]

    const int tid = threadIdx.x;
    const int tx  = tid & 31;
    const int ty  = tid >> 5;

    ull acc2[4][4];
    zero_acc(acc2);

    for (int c = 0; c < 4; ++c) {
        // As: 32 k x 64 m  (512 float4 / 256 thr = 2 each)
        #pragma unroll
        for (int i = 0; i < 2; ++i) {
            int f4 = tid + i*NT_;
            int r  = f4 >> 4;             // 0..31
            int q  = (f4 & 15) << 2;      // 0..60
            *(float4*)&As[r][q] = *(const float4*)&w2[(size_t)(k0 + c*32 + r)*F_ + m0 + q];
        }
        // Bs: 32 k x 128 n (1024 float4 / 256 thr = 4 each)
        #pragma unroll
        for (int i = 0; i < 4; ++i) {
            int f4 = tid + i*NT_;
            int r  = f4 >> 5;
            int q  = (f4 & 31) << 2;
            *(float4*)&Bs[r][q] = *(const float4*)&x[(size_t)(k0 + c*32 + r)*F_ + q];
        }
        __syncthreads();

        #pragma unroll
        for (int k = 0; k < 32; ++k) {
            ull a2[4];
            {
                ulonglong2 t0 = *(const ulonglong2*)&As[k][ty*8];
                ulonglong2 t1 = *(const ulonglong2*)&As[k][ty*8 + 4];
                a2[0] = t0.x; a2[1] = t0.y; a2[2] = t1.x; a2[3] = t1.y;
            }
            float4 bv = *(const float4*)&Bs[k][tx*4];
            ull b2[4] = { dup2(bv.x), dup2(bv.y), dup2(bv.z), dup2(bv.w) };
            #pragma unroll
            for (int p = 0; p < 4; ++p)
                #pragma unroll
                for (int j = 0; j < 4; ++j)
                    acc2[p][j] = ffma2(a2[p], b2[j], acc2[p][j]);
        }
        __syncthreads();
    }

    float* out = Spart + ((size_t)b*NSPLIT_ + split)*F_*F_;
    #pragma unroll
    for (int p = 0; p < 4; ++p) {
        float v0[4], v1[4];
        #pragma unroll
        for (int j = 0; j < 4; ++j) {
            float2 f = unpk(acc2[p][j]);
            v0[j] = f.x; v1[j] = f.y;
        }
        *(float4*)&out[(size_t)(m0 + ty*8 + 2*p    )*F_ + tx*4] = *(float4*)&v0[0];
        *(float4*)&out[(size_t)(m0 + ty*8 + 2*p + 1)*F_ + tx*4] = *(float4*)&v1[0];
    }
}

// Deterministic float4 reduction of split-K partials
__global__ void __launch_bounds__(256) reduce_S(
    const float4* __restrict__ Sp, float4* __restrict__ S)
{
    int idx = blockIdx.x*256 + threadIdx.x;
    int b   = idx >> 12;
    int ij  = idx & 4095;
    const float4* p = Sp + (size_t)b*NSPLIT_*4096 + ij;
    float4 s = p[0];
    #pragma unroll
    for (int t = 1; t < NSPLIT_; ++t) {
        float4 v = p[(size_t)t*4096];
        s.x += v.x; s.y += v.y; s.z += v.z; s.w += v.w;
    }
    S[idx] = s;
}

// ---------------------------------------------------------------------------
// Fused: msg = (w1@S[b] - diag.*x)/(N-1), then out = lrelu(msg@W5+b5) + x.
// 64-row tiles, 256 threads, 2 CTAs/SM.
// ---------------------------------------------------------------------------
__global__ void __launch_bounds__(NT_, 2) k_msg_out(
    const float* __restrict__ w1, const float* __restrict__ diag,
    const float* __restrict__ x,  const float* __restrict__ S,
    const float* __restrict__ W5, const float* __restrict__ b5,
    float* __restrict__ out)
{
    const int row0 = blockIdx.x * 64;
    const int b    = row0 >> 11;
    const float* Sb = S + (size_t)b*F_*F_;

    __shared__ float XsT[32][PADT_];
    __shared__ float Ws[32][128];
    __shared__ float dsh[64];

    const int tid = threadIdx.x;
    const int tx  = tid & 31;
    const int ty  = tid >> 5;

    if (tid < 64) dsh[tid] = diag[row0 + tid];

    ull acc2[4][4];
    zero_acc(acc2);

    // ---- stage 1: acc = w1 @ Sb ----
    for (int c = 0; c < 4; ++c) {
        load_XT_chunk(w1, row0, c, tid, XsT);
        load_W_chunk(Sb, c, tid, Ws);
        __syncthreads();
        mac_chunk(XsT, Ws, tx, ty, acc2);
        __syncthreads();
    }

    // msg values in registers (8 rows x 4 cols)
    float msgv[8][4];
    #pragma unroll
    for (int p = 0; p < 4; ++p) {
        #pragma unroll
        for (int h = 0; h < 2; ++h) {
            const int i = 2*p + h;
            const int m = ty*8 + i;
            const size_t r = (size_t)(row0 + m);
            const float d = dsh[m];
            float4 xv = *(const float4*)&x[r*F_ + tx*4];
            const float* px = (const float*)&xv;
            #pragma unroll
            for (int j = 0; j < 4; ++j) {
                float2 f = unpk(acc2[p][j]);
                float a = h ? f.y : f.x;
                msgv[i][j] = (a - d*px[j]) * INV_NM1_;
            }
        }
    }

    // ---- stage 2: out = lrelu(msg @ W5 + b5) + x ----
    zero_acc(acc2);
    for (int c = 0; c < 4; ++c) {
        __syncthreads();   // protect XsT from lagging stage-1/previous-chunk readers
        if ((tx >> 3) == c) {
            #pragma unroll
            for (int j = 0; j < 4; ++j) {
                int kk = (tx & 7)*4 + j;
                #pragma unroll
                for (int i = 0; i < 8; ++i)
                    XsT[kk][ty*8 + i] = msgv[i][j];
            }
        }
        load_W_chunk(W5, c, tid, Ws);
        __syncthreads();
        mac_chunk(XsT, Ws, tx, ty, acc2);
    }

    {
        float4 bb = *(const float4*)&b5[tx*4];
        const float* pb = (const float*)&bb;
        #pragma unroll
        for (int p = 0; p < 4; ++p) {
            #pragma unroll
            for (int h = 0; h < 2; ++h) {
                const size_t r = (size_t)(row0 + ty*8 + 2*p + h);
                float4 xv = *(const float4*)&x[r*F_ + tx*4];
                const float* px = (const float*)&xv;
                float v[4];
                #pragma unroll
                for (int j = 0; j < 4; ++j) {
                    float2 f = unpk(acc2[p][j]);
                    float a = h ? f.y : f.x;
                    v[j] = lrelu(a + pb[j]) + px[j];
                }
                *(float4*)&out[r*F_ + tx*4] = *(float4*)&v[0];
            }
        }
    }
}

// ---------------------------------------------------------------------------
extern "C" void kernel_launch(void* const* d_in, const int* in_sizes, int n_in,
                              void* d_out, int out_size)
{
    const float* x  = (const float*)d_in[0];
    const float* W3 = (const float*)d_in[1];
    const float* b3 = (const float*)d_in[2];
    const float* W4 = (const float*)d_in[3];
    const float* b4 = (const float*)d_in[4];
    const float* W5 = (const float*)d_in[5];
    const float* b5 = (const float*)d_in[6];
    float* out = (float*)d_out;

    float *pw1, *pw2, *pdg, *pSp, *pS;
    cudaGetSymbolAddress((void**)&pw1, g_w1);
    cudaGetSymbolAddress((void**)&pw2, g_w2);
    cudaGetSymbolAddress((void**)&pdg, g_diag);
    cudaGetSymbolAddress((void**)&pSp, g_Spart);
    cudaGetSymbolAddress((void**)&pS,  g_S);

    for (int l = 0; l < LAYERS_; ++l) {
        const float* xin = l ? out : x;
        const float* W3l = W3 + (size_t)l*F_*F_;
        const float* b3l = b3 + (size_t)l*F_;
        const float* W4l = W4 + (size_t)l*F_*F_;
        const float* b4l = b4 + (size_t)l*F_;
        const float* W5l = W5 + (size_t)l*F_*F_;
        const float* b5l = b5 + (size_t)l*F_;

        k_w1w2<<<M_/64, NT_>>>(xin, W3l, b3l, W4l, b4l, pw1, pw2, pdg);
        calc_S<<<dim3(NSPLIT_, B_, 2), NT_>>>(pw2, xin, pSp);
        reduce_S<<<(B_*F_*F_)/(4*256), 256>>>((const float4*)pSp, (float4*)pS);
        k_msg_out<<<M_/64, NT_>>>(pw1, pdg, xin, pS, W5l, b5l, out);
    }
}

// round 13
// speedup vs baseline: 1.3928x; 1.3928x over previous
#include <cuda_runtime.h>
#include <cuda_bf16.h>
#include <cstdint>

#define B_ 8
#define N_ 2048
#define F_ 128
#define M_ (B_*N_)
#define LAYERS_ 2
#define NSPLIT_ 16
#define SLOPE_ 0.1f
#define INV_NM1_ (1.0f/2047.0f)
#define PADS_ 68
#define NT_ 256
#define TE_ (F_*F_)           // 16384 elems per 128x128 matrix

typedef unsigned long long ull;
typedef __nv_bfloat16 bf16;

// ---------------- scratch (device globals) ----------------
__device__ float g_w2[M_*F_];
__device__ float g_diag[M_];
__device__ float g_Spart[B_*NSPLIT_*F_*F_];
__device__ __align__(16) bf16 g_xh[M_*F_],  g_xl[M_*F_];
__device__ __align__(16) bf16 g_w1h[M_*F_], g_w1l[M_*F_];
__device__ __align__(16) bf16 g_WBh[LAYERS_*3*TE_], g_WBl[LAYERS_*3*TE_];
__device__ __align__(16) bf16 g_Sh[B_*TE_], g_Sl[B_*TE_];

__device__ __forceinline__ float lrelu(float v){ return v>=0.f? v : SLOPE_*v; }
__device__ __forceinline__ void bsp(float v, bf16&h, bf16&l){
    h = __float2bfloat16(v); l = __float2bfloat16(v - __bfloat162float(h));
}
__device__ __forceinline__ uint32_t smem_u32(const void* p){
    uint32_t a; asm("{ .reg .u64 t; cvta.to.shared.u64 t, %1; cvt.u32.u64 %0, t; }" : "=r"(a) : "l"(p));
    return a;
}

// ---------------- MMA / ldmatrix wrappers (plain sm_80+ features) ----------------
__device__ __forceinline__ void ldsm4(uint32_t addr, uint32_t r[4]){
    asm volatile("ldmatrix.sync.aligned.m8n8.x4.shared.b16 {%0,%1,%2,%3}, [%4];"
        : "=r"(r[0]), "=r"(r[1]), "=r"(r[2]), "=r"(r[3]) : "r"(addr));
}
__device__ __forceinline__ void ldsm4t(uint32_t addr, uint32_t r[4]){
    asm volatile("ldmatrix.sync.aligned.m8n8.x4.trans.shared.b16 {%0,%1,%2,%3}, [%4];"
        : "=r"(r[0]), "=r"(r[1]), "=r"(r[2]), "=r"(r[3]) : "r"(addr));
}
__device__ __forceinline__ void mma16816(float d[4], const uint32_t a[4], const uint32_t b[2]){
    asm volatile("mma.sync.aligned.m16n8k16.row.col.f32.bf16.bf16.f32 "
        "{%0,%1,%2,%3}, {%4,%5,%6,%7}, {%8,%9}, {%0,%1,%2,%3};"
        : "+f"(d[0]), "+f"(d[1]), "+f"(d[2]), "+f"(d[3])
        : "r"(a[0]), "r"(a[1]), "r"(a[2]), "r"(a[3]), "r"(b[0]), "r"(b[1]));
}

// ---- f32x2 helpers (calc_S) ----
__device__ __forceinline__ ull dup2(float a){ ull r; asm("mov.b64 %0, {%1, %1};" : "=l"(r) : "f"(a)); return r; }
__device__ __forceinline__ ull ffma2(ull a, ull b, ull c){
    ull d; asm("fma.rn.f32x2 %0, %1, %2, %3;" : "=l"(d) : "l"(a), "l"(b), "l"(c)); return d;
}
__device__ __forceinline__ float2 unpk(ull v){ float2 f; asm("mov.b64 {%0, %1}, %2;" : "=f"(f.x), "=f"(f.y) : "l"(v)); return f; }

// smem strides (bf16 elems): A tiles 64 wide pad->72; B tiles / full A 128 wide pad->136
#define SA_ 72
#define SB_ 136
// k_w1w2 smem byte offsets
#define W_AH 0
#define W_AL 18432
#define W_B3H 36864
#define W_B3L 54272
#define W_B4H 71680
#define W_B4L 89088
#define W_SMEM 106496
// k_msg_out smem byte offsets
#define G_R0 0
#define G_R1 34816
#define G_C0 69632
#define G_C1 88064
#define G_C2 106496
#define G_C3 123904
#define G_SMEM 141312

// ---------------------------------------------------------------------------
// chunk loaders (global row-major bf16 -> padded smem)
// A chunk: 128 rows x 64 k (k window c*64), dest stride SA_
__device__ __forceinline__ void ldA(char* sm, const bf16* g, int row0, int c, int tid){
    bf16* d = (bf16*)sm;
    #pragma unroll
    for (int i = 0; i < 4; ++i) {
        int f4 = tid + i*256;
        int r = f4 >> 3, q = (f4 & 7)*8;
        *(float4*)&d[r*SA_ + q] = *(const float4*)&g[(size_t)(row0 + r)*F_ + c*64 + q];
    }
}
// B chunk: 64 k rows (k window c*64) x 128 n, dest stride SB_
__device__ __forceinline__ void ldB(char* sm, const bf16* g, int c, int tid){
    bf16* d = (bf16*)sm;
    #pragma unroll
    for (int i = 0; i < 4; ++i) {
        int f4 = tid + i*256;
        int r = f4 >> 4, q = (f4 & 15)*8;
        *(float4*)&d[r*SB_ + q] = *(const float4*)&g[(size_t)(c*64 + r)*F_ + q];
    }
}

// fragment address helpers (lane-dependent); strides in bf16 elems
__device__ __forceinline__ uint32_t aAddr(uint32_t base, int stride, int row16, int kcol, int l){
    int row = row16 + (l & 7) + ((l >> 3) & 1)*8;
    int kc  = kcol + ((l >> 4) & 1)*8;
    return base + (uint32_t)(row*stride + kc)*2;
}
__device__ __forceinline__ uint32_t bAddr(uint32_t base, int stride, int krow, int ncol, int l){
    int kr = krow + (l & 7) + ((l >> 3) & 1)*8;
    int nc = ncol + ((l >> 4) & 1)*8;
    return base + (uint32_t)(kr*stride + nc)*2;
}

// ---------------------------------------------------------------------------
// prep: split x into bf16 hi/lo (row-major)
// ---------------------------------------------------------------------------
__global__ void __launch_bounds__(256) k_splitX(const float4* __restrict__ X,
    bf16* __restrict__ xh, bf16* __restrict__ xl)
{
    int idx = blockIdx.x*256 + threadIdx.x;
    float4 v = X[idx];
    bf16 h[4], l[4];
    bsp(v.x,h[0],l[0]); bsp(v.y,h[1],l[1]); bsp(v.z,h[2],l[2]); bsp(v.w,h[3],l[3]);
    __nv_bfloat162 p0, p1;
    p0.x=h[0]; p0.y=h[1]; p1.x=h[2]; p1.y=h[3];
    uint2 u; u.x = *(uint32_t*)&p0; u.y = *(uint32_t*)&p1;
    *(uint2*)&xh[idx*4] = u;
    p0.x=l[0]; p0.y=l[1]; p1.x=l[2]; p1.y=l[3];
    u.x = *(uint32_t*)&p0; u.y = *(uint32_t*)&p1;
    *(uint2*)&xl[idx*4] = u;
}

// prep: split W3/W4/W5 (both layers) into bf16 hi/lo, same row-major layout
__global__ void __launch_bounds__(256) k_prepW(
    const float* __restrict__ W3, const float* __restrict__ W4, const float* __restrict__ W5,
    bf16* __restrict__ wh, bf16* __restrict__ wl)
{
    int idx = blockIdx.x*256 + threadIdx.x;    // 6*TE_ elements
    int m = idx >> 14, e = idx & 16383;
    int l = m / 3, w = m % 3;
    const float* W = (w==0 ? W3 : (w==1 ? W4 : W5)) + (size_t)l*TE_;
    bf16 h, lo; bsp(W[e], h, lo);
    wh[(size_t)m*TE_ + e] = h; wl[(size_t)m*TE_ + e] = lo;
}

// ---------------------------------------------------------------------------
// HMMA fused: w1 = lrelu(x@W3+b3), w2 = lrelu(x@W4+b4), diag = w1.w2
// 8 warps: warp (wid&3) -> 32-row block, (wid>>2) -> 64-col block.
// ---------------------------------------------------------------------------
__global__ void __launch_bounds__(256) k_w1w2(
    const bf16* __restrict__ xh, const bf16* __restrict__ xl,
    const bf16* __restrict__ w3h, const bf16* __restrict__ w3l,
    const bf16* __restrict__ w4h, const bf16* __restrict__ w4l,
    const float* __restrict__ b3, const float* __restrict__ b4,
    float* __restrict__ w2o, bf16* __restrict__ w1h, bf16* __restrict__ w1l,
    float* __restrict__ diag)
{
    extern __shared__ char sm[];
    __shared__ float dsh[256];
    const int tid = threadIdx.x, wid = tid>>5, l = tid&31;
    const int row0 = blockIdx.x * 128;
    const int mrow0 = (wid & 3)*32, ncol0 = (wid >> 2)*64;
    const uint32_t sb = smem_u32(sm);

    float acc3[2][8][4], acc4[2][8][4];
    #pragma unroll
    for (int mt = 0; mt < 2; ++mt)
        #pragma unroll
        for (int n = 0; n < 8; ++n)
            #pragma unroll
            for (int q = 0; q < 4; ++q) { acc3[mt][n][q] = 0.f; acc4[mt][n][q] = 0.f; }

    for (int c = 0; c < 2; ++c) {
        ldA(sm + W_AH, xh, row0, c, tid);
        ldA(sm + W_AL, xl, row0, c, tid);
        ldB(sm + W_B3H, w3h, c, tid);
        ldB(sm + W_B3L, w3l, c, tid);
        ldB(sm + W_B4H, w4h, c, tid);
        ldB(sm + W_B4L, w4l, c, tid);
        __syncthreads();

        #pragma unroll
        for (int kk = 0; kk < 4; ++kk) {
            uint32_t ah[2][4], al_[2][4];
            #pragma unroll
            for (int mt = 0; mt < 2; ++mt) {
                ldsm4(aAddr(sb + W_AH, SA_, mrow0 + mt*16, kk*16, l), ah[mt]);
                ldsm4(aAddr(sb + W_AL, SA_, mrow0 + mt*16, kk*16, l), al_[mt]);
            }
            #pragma unroll
            for (int np = 0; np < 4; ++np) {
                uint32_t b3hF[4], b3lF[4], b4hF[4], b4lF[4];
                ldsm4t(bAddr(sb + W_B3H, SB_, kk*16, ncol0 + np*16, l), b3hF);
                ldsm4t(bAddr(sb + W_B3L, SB_, kk*16, ncol0 + np*16, l), b3lF);
                ldsm4t(bAddr(sb + W_B4H, SB_, kk*16, ncol0 + np*16, l), b4hF);
                ldsm4t(bAddr(sb + W_B4L, SB_, kk*16, ncol0 + np*16, l), b4lF);
                #pragma unroll
                for (int mt = 0; mt < 2; ++mt) {
                    #pragma unroll
                    for (int hnf = 0; hnf < 2; ++hnf) {
                        int n = np*2 + hnf;
                        mma16816(acc3[mt][n], ah[mt],  &b3hF[hnf*2]);
                        mma16816(acc3[mt][n], ah[mt],  &b3lF[hnf*2]);
                        mma16816(acc3[mt][n], al_[mt], &b3hF[hnf*2]);
                        mma16816(acc4[mt][n], ah[mt],  &b4hF[hnf*2]);
                        mma16816(acc4[mt][n], ah[mt],  &b4lF[hnf*2]);
                        mma16816(acc4[mt][n], al_[mt], &b4hF[hnf*2]);
                    }
                }
            }
        }
        __syncthreads();
    }

    // epilogue: bias + lrelu, store w1 (bf16 h/l) + w2 (f32), diag partials
    float dp[2][2] = {{0.f,0.f},{0.f,0.f}};
    #pragma unroll
    for (int mt = 0; mt < 2; ++mt) {
        #pragma unroll
        for (int n = 0; n < 8; ++n) {
            int col = ncol0 + n*8 + (l & 3)*2;
            float bb3a = b3[col], bb3b = b3[col+1];
            float bb4a = b4[col], bb4b = b4[col+1];
            #pragma unroll
            for (int hf = 0; hf < 2; ++hf) {
                int row = mrow0 + mt*16 + (l >> 2) + hf*8;
                float v1a = lrelu(acc3[mt][n][hf*2+0] + bb3a);
                float v1b = lrelu(acc3[mt][n][hf*2+1] + bb3b);
                float v2a = lrelu(acc4[mt][n][hf*2+0] + bb4a);
                float v2b = lrelu(acc4[mt][n][hf*2+1] + bb4b);
                dp[mt][hf] += v1a*v2a + v1b*v2b;
                size_t gg = (size_t)(row0 + row)*F_ + col;
                float2 w2v; w2v.x = v2a; w2v.y = v2b;
                *(float2*)&w2o[gg] = w2v;
                bf16 h0,l0,h1,l1; bsp(v1a,h0,l0); bsp(v1b,h1,l1);
                __nv_bfloat162 p;
                p.x=h0; p.y=h1; *(__nv_bfloat162*)&w1h[gg] = p;
                p.x=l0; p.y=l1; *(__nv_bfloat162*)&w1l[gg] = p;
            }
        }
    }
    // quad-reduce diag partials (lanes sharing l>>2 have same rows)
    #pragma unroll
    for (int mt = 0; mt < 2; ++mt)
        #pragma unroll
        for (int hf = 0; hf < 2; ++hf) {
            float d = dp[mt][hf];
            d += __shfl_xor_sync(0xffffffffu, d, 1);
            d += __shfl_xor_sync(0xffffffffu, d, 2);
            if ((l & 3) == 0) {
                int row = mrow0 + mt*16 + (l >> 2) + hf*8;
                dsh[(wid >> 2)*128 + row] = d;
            }
        }
    __syncthreads();
    if (tid < 128) diag[row0 + tid] = dsh[tid] + dsh[128 + tid];
}

// ---------------------------------------------------------------------------
// calc_S: split-K partials of S[b] = w2^T @ x (f32x2, unchanged)
// ---------------------------------------------------------------------------
__global__ void __launch_bounds__(NT_, 2) calc_S(
    const float* __restrict__ w2, const float* __restrict__ x,
    float* __restrict__ Spart)
{
    const int split = blockIdx.x, b = blockIdx.y, m0 = blockIdx.z*64;
    const int k0 = b*N_ + split*128;
    __shared__ float As[32][PADS_];
    __shared__ float Bs[32][128];
    const int tid = threadIdx.x, tx = tid&31, ty = tid>>5;

    ull acc2[4][4];
    #pragma unroll
    for (int p = 0; p < 4; ++p)
        #pragma unroll
        for (int j = 0; j < 4; ++j) acc2[p][j] = 0ull;

    for (int c = 0; c < 4; ++c) {
        #pragma unroll
        for (int i = 0; i < 2; ++i) {
            int f4 = tid + i*NT_;
            int r = f4 >> 4, q = (f4 & 15) << 2;
            *(float4*)&As[r][q] = *(const float4*)&w2[(size_t)(k0 + c*32 + r)*F_ + m0 + q];
        }
        #pragma unroll
        for (int i = 0; i < 4; ++i) {
            int f4 = tid + i*NT_;
            int r = f4 >> 5, q = (f4 & 31) << 2;
            *(float4*)&Bs[r][q] = *(const float4*)&x[(size_t)(k0 + c*32 + r)*F_ + q];
        }
        __syncthreads();
        #pragma unroll
        for (int k = 0; k < 32; ++k) {
            ull a2[4];
            {
                ulonglong2 t0 = *(const ulonglong2*)&As[k][ty*8];
                ulonglong2 t1 = *(const ulonglong2*)&As[k][ty*8 + 4];
                a2[0]=t0.x; a2[1]=t0.y; a2[2]=t1.x; a2[3]=t1.y;
            }
            float4 bv = *(const float4*)&Bs[k][tx*4];
            ull b2[4] = { dup2(bv.x), dup2(bv.y), dup2(bv.z), dup2(bv.w) };
            #pragma unroll
            for (int p = 0; p < 4; ++p)
                #pragma unroll
                for (int j = 0; j < 4; ++j) acc2[p][j] = ffma2(a2[p], b2[j], acc2[p][j]);
        }
        __syncthreads();
    }
    float* out = Spart + ((size_t)b*NSPLIT_ + split)*F_*F_;
    #pragma unroll
    for (int p = 0; p < 4; ++p) {
        float v0[4], v1[4];
        #pragma unroll
        for (int j = 0; j < 4; ++j) { float2 f = unpk(acc2[p][j]); v0[j]=f.x; v1[j]=f.y; }
        *(float4*)&out[(size_t)(m0 + ty*8 + 2*p    )*F_ + tx*4] = *(float4*)&v0[0];
        *(float4*)&out[(size_t)(m0 + ty*8 + 2*p + 1)*F_ + tx*4] = *(float4*)&v1[0];
    }
}

// reduce split-K partials -> S bf16 hi/lo (row-major [b][f][g])
__global__ void __launch_bounds__(256) k_reduceS(
    const float* __restrict__ Sp, bf16* __restrict__ sh, bf16* __restrict__ sl)
{
    int idx = blockIdx.x*256 + threadIdx.x;   // B_*TE_
    int b = idx >> 14, fg = idx & 16383;
    const float* p = Sp + (size_t)b*NSPLIT_*16384 + fg;
    float s = 0.f;
    #pragma unroll
    for (int t = 0; t < NSPLIT_; ++t) s += p[(size_t)t*16384];
    bf16 h, lo; bsp(s, h, lo);
    sh[idx] = h; sl[idx] = lo;
}

// ---------------------------------------------------------------------------
// HMMA fused: msg = (w1@S - diag.*x)/(N-1); out = lrelu(msg@W5+b5) + x;
// also emits next-layer x split (nxh/nxl).
// ---------------------------------------------------------------------------
__global__ void __launch_bounds__(256) k_msg_out(
    const bf16* __restrict__ w1h, const bf16* __restrict__ w1l,
    const float* __restrict__ diag, const float* __restrict__ x,
    const bf16* __restrict__ sh, const bf16* __restrict__ sl,
    const bf16* __restrict__ w5h, const bf16* __restrict__ w5l,
    const float* __restrict__ b5,
    float* __restrict__ out, bf16* __restrict__ nxh, bf16* __restrict__ nxl)
{
    extern __shared__ char sm[];
    __shared__ float ds[128];
    const int tid = threadIdx.x, wid = tid>>5, l = tid&31;
    const int row0 = blockIdx.x * 128, b = blockIdx.x >> 4;
    const int mrow0 = (wid & 3)*32, ncol0 = (wid >> 2)*64;
    const uint32_t sb = smem_u32(sm);

    if (tid < 128) ds[tid] = diag[row0 + tid];

    float acc[2][8][4];
    #pragma unroll
    for (int mt = 0; mt < 2; ++mt)
        #pragma unroll
        for (int n = 0; n < 8; ++n)
            #pragma unroll
            for (int q = 0; q < 4; ++q) acc[mt][n][q] = 0.f;

    // ---- stage 1: acc = w1 @ S ----
    for (int c = 0; c < 2; ++c) {
        ldA(sm + G_C0, w1h, row0, c, tid);
        ldA(sm + G_C1, w1l, row0, c, tid);
        ldB(sm + G_C2, sh + (size_t)b*TE_, c, tid);
        ldB(sm + G_C3, sl + (size_t)b*TE_, c, tid);
        __syncthreads();
        #pragma unroll
        for (int kk = 0; kk < 4; ++kk) {
            uint32_t ah[2][4], al_[2][4];
            #pragma unroll
            for (int mt = 0; mt < 2; ++mt) {
                ldsm4(aAddr(sb + G_C0, SA_, mrow0 + mt*16, kk*16, l), ah[mt]);
                ldsm4(aAddr(sb + G_C1, SA_, mrow0 + mt*16, kk*16, l), al_[mt]);
            }
            #pragma unroll
            for (int np = 0; np < 4; ++np) {
                uint32_t bhF[4], blF[4];
                ldsm4t(bAddr(sb + G_C2, SB_, kk*16, ncol0 + np*16, l), bhF);
                ldsm4t(bAddr(sb + G_C3, SB_, kk*16, ncol0 + np*16, l), blF);
                #pragma unroll
                for (int mt = 0; mt < 2; ++mt) {
                    #pragma unroll
                    for (int hnf = 0; hnf < 2; ++hnf) {
                        int n = np*2 + hnf;
                        mma16816(acc[mt][n], ah[mt],  &bhF[hnf*2]);
                        mma16816(acc[mt][n], ah[mt],  &blF[hnf*2]);
                        mma16816(acc[mt][n], al_[mt], &bhF[hnf*2]);
                    }
                }
            }
        }
        __syncthreads();
    }

    // msg: (acc - diag*x)/(N-1) -> bf16 h/l into R0/R1 (full 128x128, stride SB_)
    {
        bf16* mh = (bf16*)(sm + G_R0);
        bf16* ml = (bf16*)(sm + G_R1);
        #pragma unroll
        for (int mt = 0; mt < 2; ++mt) {
            #pragma unroll
            for (int hf = 0; hf < 2; ++hf) {
                int row = mrow0 + mt*16 + (l >> 2) + hf*8;
                float dv = ds[row];
                size_t gg = (size_t)(row0 + row)*F_;
                #pragma unroll
                for (int n = 0; n < 8; ++n) {
                    int col = ncol0 + n*8 + (l & 3)*2;
                    float2 xv = *(const float2*)&x[gg + col];
                    float a0 = (acc[mt][n][hf*2+0] - dv*xv.x) * INV_NM1_;
                    float a1 = (acc[mt][n][hf*2+1] - dv*xv.y) * INV_NM1_;
                    bf16 h0,l0,h1,l1; bsp(a0,h0,l0); bsp(a1,h1,l1);
                    __nv_bfloat162 p;
                    p.x=h0; p.y=h1; *(__nv_bfloat162*)&mh[row*SB_ + col] = p;
                    p.x=l0; p.y=l1; *(__nv_bfloat162*)&ml[row*SB_ + col] = p;
                }
            }
        }
    }
    __syncthreads();

    // ---- stage 2: acc = msg @ W5 ----
    #pragma unroll
    for (int mt = 0; mt < 2; ++mt)
        #pragma unroll
        for (int n = 0; n < 8; ++n)
            #pragma unroll
            for (int q = 0; q < 4; ++q) acc[mt][n][q] = 0.f;

    for (int c = 0; c < 2; ++c) {
        ldB(sm + G_C2, w5h, c, tid);
        ldB(sm + G_C3, w5l, c, tid);
        __syncthreads();
        #pragma unroll
        for (int kk = 0; kk < 4; ++kk) {
            uint32_t ah[2][4], al_[2][4];
            #pragma unroll
            for (int mt = 0; mt < 2; ++mt) {
                ldsm4(aAddr(sb + G_R0, SB_, mrow0 + mt*16, c*64 + kk*16, l), ah[mt]);
                ldsm4(aAddr(sb + G_R1, SB_, mrow0 + mt*16, c*64 + kk*16, l), al_[mt]);
            }
            #pragma unroll
            for (int np = 0; np < 4; ++np) {
                uint32_t bhF[4], blF[4];
                ldsm4t(bAddr(sb + G_C2, SB_, kk*16, ncol0 + np*16, l), bhF);
                ldsm4t(bAddr(sb + G_C3, SB_, kk*16, ncol0 + np*16, l), blF);
                #pragma unroll
                for (int mt = 0; mt < 2; ++mt) {
                    #pragma unroll
                    for (int hnf = 0; hnf < 2; ++hnf) {
                        int n = np*2 + hnf;
                        mma16816(acc[mt][n], ah[mt],  &bhF[hnf*2]);
                        mma16816(acc[mt][n], ah[mt],  &blF[hnf*2]);
                        mma16816(acc[mt][n], al_[mt], &bhF[hnf*2]);
                    }
                }
            }
        }
        __syncthreads();
    }

    // epilogue: out = lrelu(acc + b5) + x; next-layer split
    #pragma unroll
    for (int mt = 0; mt < 2; ++mt) {
        #pragma unroll
        for (int n = 0; n < 8; ++n) {
            int col = ncol0 + n*8 + (l & 3)*2;
            float ba = b5[col], bb = b5[col+1];
            #pragma unroll
            for (int hf = 0; hf < 2; ++hf) {
                int row = mrow0 + mt*16 + (l >> 2) + hf*8;
                size_t gg = (size_t)(row0 + row)*F_ + col;
                float2 xv = *(const float2*)&x[gg];
                float v0 = lrelu(acc[mt][n][hf*2+0] + ba) + xv.x;
                float v1 = lrelu(acc[mt][n][hf*2+1] + bb) + xv.y;
                float2 ov; ov.x = v0; ov.y = v1;
                *(float2*)&out[gg] = ov;
                bf16 h0,l0,h1,l1; bsp(v0,h0,l0); bsp(v1,h1,l1);
                __nv_bfloat162 p;
                p.x=h0; p.y=h1; *(__nv_bfloat162*)&nxh[gg] = p;
                p.x=l0; p.y=l1; *(__nv_bfloat162*)&nxl[gg] = p;
            }
        }
    }
}

// ---------------------------------------------------------------------------
extern "C" void kernel_launch(void* const* d_in, const int* in_sizes, int n_in,
                              void* d_out, int out_size)
{
    const float* x  = (const float*)d_in[0];
    const float* W3 = (const float*)d_in[1];
    const float* b3 = (const float*)d_in[2];
    const float* W4 = (const float*)d_in[3];
    const float* b4 = (const float*)d_in[4];
    const float* W5 = (const float*)d_in[5];
    const float* b5 = (const float*)d_in[6];
    float* out = (float*)d_out;

    cudaFuncSetAttribute(k_w1w2,    cudaFuncAttributeMaxDynamicSharedMemorySize, W_SMEM);
    cudaFuncSetAttribute(k_msg_out, cudaFuncAttributeMaxDynamicSharedMemorySize, G_SMEM);

    float *pw2, *pdg, *pSp;
    bf16 *pxh, *pxl, *pw1h, *pw1l, *pWh, *pWl, *pSh, *pSl;
    cudaGetSymbolAddress((void**)&pw2,  g_w2);
    cudaGetSymbolAddress((void**)&pdg,  g_diag);
    cudaGetSymbolAddress((void**)&pSp,  g_Spart);
    cudaGetSymbolAddress((void**)&pxh,  g_xh);
    cudaGetSymbolAddress((void**)&pxl,  g_xl);
    cudaGetSymbolAddress((void**)&pw1h, g_w1h);
    cudaGetSymbolAddress((void**)&pw1l, g_w1l);
    cudaGetSymbolAddress((void**)&pWh,  g_WBh);
    cudaGetSymbolAddress((void**)&pWl,  g_WBl);
    cudaGetSymbolAddress((void**)&pSh,  g_Sh);
    cudaGetSymbolAddress((void**)&pSl,  g_Sl);

    k_splitX<<<(M_*F_/4)/256, 256>>>((const float4*)x, pxh, pxl);
    k_prepW<<<(6*TE_)/256, 256>>>(W3, W4, W5, pWh, pWl);

    for (int l = 0; l < LAYERS_; ++l) {
        const float* xinF = l ? out : x;
        const bf16* Wh = pWh + (size_t)l*3*TE_;
        const bf16* Wl = pWl + (size_t)l*3*TE_;

        k_w1w2<<<M_/128, 256, W_SMEM>>>(pxh, pxl,
                                        Wh, Wl, Wh + TE_, Wl + TE_,
                                        b3 + l*F_, b4 + l*F_,
                                        pw2, pw1h, pw1l, pdg);
        calc_S<<<dim3(NSPLIT_, B_, 2), NT_>>>(pw2, xinF, pSp);
        k_reduceS<<<(B_*TE_)/256, 256>>>(pSp, pSh, pSl);
        k_msg_out<<<M_/128, 256, G_SMEM>>>(pw1h, pw1l, pdg, xinF,
                                           pSh, pSl,
                                           Wh + 2*TE_, Wl + 2*TE_,
                                           b5 + l*F_, out, pxh, pxl);
    }
}

// round 14
// speedup vs baseline: 1.5424x; 1.1074x over previous
#include <cuda_runtime.h>
#include <cuda_bf16.h>
#include <cstdint>

#define B_ 8
#define N_ 2048
#define F_ 128
#define M_ (B_*N_)
#define LAYERS_ 2
#define NSPLIT_ 16
#define SLOPE_ 0.1f
#define INV_NM1_ (1.0f/2047.0f)
#define TE_ (F_*F_)           // 16384 elems per 128x128 matrix

typedef unsigned long long ull;
typedef __nv_bfloat16 bf16;

// ---------------- scratch (device globals) ----------------
__device__ float g_diag[M_];
__device__ float g_Spart[B_*NSPLIT_*F_*F_];
__device__ __align__(16) bf16 g_xh[M_*F_],  g_xl[M_*F_];
__device__ __align__(16) bf16 g_w1h[M_*F_], g_w1l[M_*F_];
__device__ __align__(16) bf16 g_w2h[M_*F_], g_w2l[M_*F_];
__device__ __align__(16) bf16 g_WBh[LAYERS_*3*TE_], g_WBl[LAYERS_*3*TE_];
__device__ __align__(16) bf16 g_Sh[B_*TE_], g_Sl[B_*TE_];

__device__ __forceinline__ float lrelu(float v){ return v>=0.f? v : SLOPE_*v; }
__device__ __forceinline__ void bsp(float v, bf16&h, bf16&l){
    h = __float2bfloat16(v); l = __float2bfloat16(v - __bfloat162float(h));
}
__device__ __forceinline__ uint32_t smem_u32(const void* p){
    uint32_t a; asm("{ .reg .u64 t; cvta.to.shared.u64 t, %1; cvt.u32.u64 %0, t; }" : "=r"(a) : "l"(p));
    return a;
}

// ---------------- MMA / ldmatrix wrappers ----------------
__device__ __forceinline__ void ldsm4(uint32_t addr, uint32_t r[4]){
    asm volatile("ldmatrix.sync.aligned.m8n8.x4.shared.b16 {%0,%1,%2,%3}, [%4];"
        : "=r"(r[0]), "=r"(r[1]), "=r"(r[2]), "=r"(r[3]) : "r"(addr));
}
__device__ __forceinline__ void ldsm4t(uint32_t addr, uint32_t r[4]){
    asm volatile("ldmatrix.sync.aligned.m8n8.x4.trans.shared.b16 {%0,%1,%2,%3}, [%4];"
        : "=r"(r[0]), "=r"(r[1]), "=r"(r[2]), "=r"(r[3]) : "r"(addr));
}
__device__ __forceinline__ void mma16816(float d[4], const uint32_t a[4], const uint32_t b[2]){
    asm volatile("mma.sync.aligned.m16n8k16.row.col.f32.bf16.bf16.f32 "
        "{%0,%1,%2,%3}, {%4,%5,%6,%7}, {%8,%9}, {%0,%1,%2,%3};"
        : "+f"(d[0]), "+f"(d[1]), "+f"(d[2]), "+f"(d[3])
        : "r"(a[0]), "r"(a[1]), "r"(a[2]), "r"(a[3]), "r"(b[0]), "r"(b[1]));
}

// smem strides (bf16 elems)
#define SA_ 72
#define SB_ 136
// k_w1w2 smem byte offsets
#define W_AH 0
#define W_AL 18432
#define W_B3H 36864
#define W_B3L 54272
#define W_B4H 71680
#define W_B4L 89088
#define W_SMEM 106496
// k_msg_out smem byte offsets
#define G_R0 0
#define G_R1 34816
#define G_C0 69632
#define G_C1 88064
#define G_C2 106496
#define G_C3 123904
#define G_SMEM 141312
// calc_S smem byte offsets (4 tiles of 64x128 bf16, stride SB_)
#define S_AH 0
#define S_AL 17408
#define S_BH 34816
#define S_BL 52224
#define S_SMEM 69632

// ---------------------------------------------------------------------------
// chunk loaders
__device__ __forceinline__ void ldA(char* sm, const bf16* g, int row0, int c, int tid){
    bf16* d = (bf16*)sm;
    #pragma unroll
    for (int i = 0; i < 4; ++i) {
        int f4 = tid + i*256;
        int r = f4 >> 3, q = (f4 & 7)*8;
        *(float4*)&d[r*SA_ + q] = *(const float4*)&g[(size_t)(row0 + r)*F_ + c*64 + q];
    }
}
__device__ __forceinline__ void ldB(char* sm, const bf16* g, int c, int tid){
    bf16* d = (bf16*)sm;
    #pragma unroll
    for (int i = 0; i < 4; ++i) {
        int f4 = tid + i*256;
        int r = f4 >> 4, q = (f4 & 15)*8;
        *(float4*)&d[r*SB_ + q] = *(const float4*)&g[(size_t)(c*64 + r)*F_ + q];
    }
}

// fragment address helpers (lane-dependent); strides in bf16 elems
__device__ __forceinline__ uint32_t aAddr(uint32_t base, int stride, int row16, int kcol, int l){
    int row = row16 + (l & 7) + ((l >> 3) & 1)*8;
    int kc  = kcol + ((l >> 4) & 1)*8;
    return base + (uint32_t)(row*stride + kc)*2;
}
__device__ __forceinline__ uint32_t bAddr(uint32_t base, int stride, int krow, int ncol, int l){
    int kr = krow + (l & 7) + ((l >> 3) & 1)*8;
    int nc = ncol + ((l >> 4) & 1)*8;
    return base + (uint32_t)(kr*stride + nc)*2;
}
// A-operand via trans load of a [k][f]-stored tile (= normal load of [f][k]):
// m-half <- bit3 of lane, k-half <- bit4 (inverse pairing of bAddr).
__device__ __forceinline__ uint32_t atAddr(uint32_t base, int stride, int krow, int fcol, int l){
    int kr = krow + (l & 7) + ((l >> 4) & 1)*8;
    int fc = fcol + ((l >> 3) & 1)*8;
    return base + (uint32_t)(kr*stride + fc)*2;
}

// ---------------------------------------------------------------------------
// prep: split x into bf16 hi/lo (row-major)
__global__ void __launch_bounds__(256) k_splitX(const float4* __restrict__ X,
    bf16* __restrict__ xh, bf16* __restrict__ xl)
{
    int idx = blockIdx.x*256 + threadIdx.x;
    float4 v = X[idx];
    bf16 h[4], l[4];
    bsp(v.x,h[0],l[0]); bsp(v.y,h[1],l[1]); bsp(v.z,h[2],l[2]); bsp(v.w,h[3],l[3]);
    __nv_bfloat162 p0, p1;
    p0.x=h[0]; p0.y=h[1]; p1.x=h[2]; p1.y=h[3];
    uint2 u; u.x = *(uint32_t*)&p0; u.y = *(uint32_t*)&p1;
    *(uint2*)&xh[idx*4] = u;
    p0.x=l[0]; p0.y=l[1]; p1.x=l[2]; p1.y=l[3];
    u.x = *(uint32_t*)&p0; u.y = *(uint32_t*)&p1;
    *(uint2*)&xl[idx*4] = u;
}

// prep: split W3/W4/W5 (both layers) into bf16 hi/lo
__global__ void __launch_bounds__(256) k_prepW(
    const float* __restrict__ W3, const float* __restrict__ W4, const float* __restrict__ W5,
    bf16* __restrict__ wh, bf16* __restrict__ wl)
{
    int idx = blockIdx.x*256 + threadIdx.x;
    int m = idx >> 14, e = idx & 16383;
    int l = m / 3, w = m % 3;
    const float* W = (w==0 ? W3 : (w==1 ? W4 : W5)) + (size_t)l*TE_;
    bf16 h, lo; bsp(W[e], h, lo);
    wh[(size_t)m*TE_ + e] = h; wl[(size_t)m*TE_ + e] = lo;
}

// ---------------------------------------------------------------------------
// HMMA fused: w1 = lrelu(x@W3+b3), w2 = lrelu(x@W4+b4), diag = w1.w2
// w1 AND w2 stored as bf16 hi/lo.
// ---------------------------------------------------------------------------
__global__ void __launch_bounds__(256) k_w1w2(
    const bf16* __restrict__ xh, const bf16* __restrict__ xl,
    const bf16* __restrict__ w3h, const bf16* __restrict__ w3l,
    const bf16* __restrict__ w4h, const bf16* __restrict__ w4l,
    const float* __restrict__ b3, const float* __restrict__ b4,
    bf16* __restrict__ w2h, bf16* __restrict__ w2l,
    bf16* __restrict__ w1h, bf16* __restrict__ w1l,
    float* __restrict__ diag)
{
    extern __shared__ char sm[];
    __shared__ float dsh[256];
    const int tid = threadIdx.x, wid = tid>>5, l = tid&31;
    const int row0 = blockIdx.x * 128;
    const int mrow0 = (wid & 3)*32, ncol0 = (wid >> 2)*64;
    const uint32_t sb = smem_u32(sm);

    float acc3[2][8][4], acc4[2][8][4];
    #pragma unroll
    for (int mt = 0; mt < 2; ++mt)
        #pragma unroll
        for (int n = 0; n < 8; ++n)
            #pragma unroll
            for (int q = 0; q < 4; ++q) { acc3[mt][n][q] = 0.f; acc4[mt][n][q] = 0.f; }

    for (int c = 0; c < 2; ++c) {
        ldA(sm + W_AH, xh, row0, c, tid);
        ldA(sm + W_AL, xl, row0, c, tid);
        ldB(sm + W_B3H, w3h, c, tid);
        ldB(sm + W_B3L, w3l, c, tid);
        ldB(sm + W_B4H, w4h, c, tid);
        ldB(sm + W_B4L, w4l, c, tid);
        __syncthreads();

        #pragma unroll
        for (int kk = 0; kk < 4; ++kk) {
            uint32_t ah[2][4], al_[2][4];
            #pragma unroll
            for (int mt = 0; mt < 2; ++mt) {
                ldsm4(aAddr(sb + W_AH, SA_, mrow0 + mt*16, kk*16, l), ah[mt]);
                ldsm4(aAddr(sb + W_AL, SA_, mrow0 + mt*16, kk*16, l), al_[mt]);
            }
            #pragma unroll
            for (int np = 0; np < 4; ++np) {
                uint32_t b3hF[4], b3lF[4], b4hF[4], b4lF[4];
                ldsm4t(bAddr(sb + W_B3H, SB_, kk*16, ncol0 + np*16, l), b3hF);
                ldsm4t(bAddr(sb + W_B3L, SB_, kk*16, ncol0 + np*16, l), b3lF);
                ldsm4t(bAddr(sb + W_B4H, SB_, kk*16, ncol0 + np*16, l), b4hF);
                ldsm4t(bAddr(sb + W_B4L, SB_, kk*16, ncol0 + np*16, l), b4lF);
                #pragma unroll
                for (int mt = 0; mt < 2; ++mt) {
                    #pragma unroll
                    for (int hnf = 0; hnf < 2; ++hnf) {
                        int n = np*2 + hnf;
                        mma16816(acc3[mt][n], ah[mt],  &b3hF[hnf*2]);
                        mma16816(acc3[mt][n], ah[mt],  &b3lF[hnf*2]);
                        mma16816(acc3[mt][n], al_[mt], &b3hF[hnf*2]);
                        mma16816(acc4[mt][n], ah[mt],  &b4hF[hnf*2]);
                        mma16816(acc4[mt][n], ah[mt],  &b4lF[hnf*2]);
                        mma16816(acc4[mt][n], al_[mt], &b4hF[hnf*2]);
                    }
                }
            }
        }
        __syncthreads();
    }

    float dp[2][2] = {{0.f,0.f},{0.f,0.f}};
    #pragma unroll
    for (int mt = 0; mt < 2; ++mt) {
        #pragma unroll
        for (int n = 0; n < 8; ++n) {
            int col = ncol0 + n*8 + (l & 3)*2;
            float bb3a = b3[col], bb3b = b3[col+1];
            float bb4a = b4[col], bb4b = b4[col+1];
            #pragma unroll
            for (int hf = 0; hf < 2; ++hf) {
                int row = mrow0 + mt*16 + (l >> 2) + hf*8;
                float v1a = lrelu(acc3[mt][n][hf*2+0] + bb3a);
                float v1b = lrelu(acc3[mt][n][hf*2+1] + bb3b);
                float v2a = lrelu(acc4[mt][n][hf*2+0] + bb4a);
                float v2b = lrelu(acc4[mt][n][hf*2+1] + bb4b);
                dp[mt][hf] += v1a*v2a + v1b*v2b;
                size_t gg = (size_t)(row0 + row)*F_ + col;
                bf16 h0,l0,h1,l1;
                bsp(v1a,h0,l0); bsp(v1b,h1,l1);
                __nv_bfloat162 p;
                p.x=h0; p.y=h1; *(__nv_bfloat162*)&w1h[gg] = p;
                p.x=l0; p.y=l1; *(__nv_bfloat162*)&w1l[gg] = p;
                bsp(v2a,h0,l0); bsp(v2b,h1,l1);
                p.x=h0; p.y=h1; *(__nv_bfloat162*)&w2h[gg] = p;
                p.x=l0; p.y=l1; *(__nv_bfloat162*)&w2l[gg] = p;
            }
        }
    }
    #pragma unroll
    for (int mt = 0; mt < 2; ++mt)
        #pragma unroll
        for (int hf = 0; hf < 2; ++hf) {
            float d = dp[mt][hf];
            d += __shfl_xor_sync(0xffffffffu, d, 1);
            d += __shfl_xor_sync(0xffffffffu, d, 2);
            if ((l & 3) == 0) {
                int row = mrow0 + mt*16 + (l >> 2) + hf*8;
                dsh[(wid >> 2)*128 + row] = d;
            }
        }
    __syncthreads();
    if (tid < 128) diag[row0 + tid] = dsh[tid] + dsh[128 + tid];
}

// ---------------------------------------------------------------------------
// HMMA calc_S: partial S[b] = w2[k0:k0+128]^T @ x[k0:k0+128] (f32 partials).
// A = w2^T via trans-load of [k][f] tiles (atAddr). grid = (NSPLIT_, B_).
// ---------------------------------------------------------------------------
__global__ void __launch_bounds__(256) calc_S(
    const bf16* __restrict__ w2h, const bf16* __restrict__ w2l,
    const bf16* __restrict__ xh,  const bf16* __restrict__ xl,
    float* __restrict__ Spart)
{
    extern __shared__ char sm[];
    const int tid = threadIdx.x, wid = tid>>5, l = tid&31;
    const int split = blockIdx.x, b = blockIdx.y;
    const size_t k0F = (size_t)(b*N_ + split*128)*F_;
    const int mrow0 = (wid & 3)*32, ncol0 = (wid >> 2)*64;   // f block, g block
    const uint32_t sb = smem_u32(sm);

    float acc[2][8][4];
    #pragma unroll
    for (int mt = 0; mt < 2; ++mt)
        #pragma unroll
        for (int n = 0; n < 8; ++n)
            #pragma unroll
            for (int q = 0; q < 4; ++q) acc[mt][n][q] = 0.f;

    for (int c = 0; c < 2; ++c) {
        ldB(sm + S_AH, w2h + k0F, c, tid);   // [k][f] chunk
        ldB(sm + S_AL, w2l + k0F, c, tid);
        ldB(sm + S_BH, xh + k0F, c, tid);    // [k][g] chunk
        ldB(sm + S_BL, xl + k0F, c, tid);
        __syncthreads();

        #pragma unroll
        for (int kk = 0; kk < 4; ++kk) {
            uint32_t ah[2][4], al_[2][4];
            #pragma unroll
            for (int mt = 0; mt < 2; ++mt) {
                ldsm4t(atAddr(sb + S_AH, SB_, kk*16, mrow0 + mt*16, l), ah[mt]);
                ldsm4t(atAddr(sb + S_AL, SB_, kk*16, mrow0 + mt*16, l), al_[mt]);
            }
            #pragma unroll
            for (int np = 0; np < 4; ++np) {
                uint32_t bhF[4], blF[4];
                ldsm4t(bAddr(sb + S_BH, SB_, kk*16, ncol0 + np*16, l), bhF);
                ldsm4t(bAddr(sb + S_BL, SB_, kk*16, ncol0 + np*16, l), blF);
                #pragma unroll
                for (int mt = 0; mt < 2; ++mt) {
                    #pragma unroll
                    for (int hnf = 0; hnf < 2; ++hnf) {
                        int n = np*2 + hnf;
                        mma16816(acc[mt][n], ah[mt],  &bhF[hnf*2]);
                        mma16816(acc[mt][n], ah[mt],  &blF[hnf*2]);
                        mma16816(acc[mt][n], al_[mt], &bhF[hnf*2]);
                    }
                }
            }
        }
        __syncthreads();
    }

    float* out = Spart + ((size_t)b*NSPLIT_ + split)*TE_;
    #pragma unroll
    for (int mt = 0; mt < 2; ++mt) {
        #pragma unroll
        for (int n = 0; n < 8; ++n) {
            int col = ncol0 + n*8 + (l & 3)*2;
            #pragma unroll
            for (int hf = 0; hf < 2; ++hf) {
                int row = mrow0 + mt*16 + (l >> 2) + hf*8;
                float2 v; v.x = acc[mt][n][hf*2+0]; v.y = acc[mt][n][hf*2+1];
                *(float2*)&out[(size_t)row*F_ + col] = v;
            }
        }
    }
}

// reduce split-K partials -> S bf16 hi/lo (row-major [b][f][g])
__global__ void __launch_bounds__(256) k_reduceS(
    const float* __restrict__ Sp, bf16* __restrict__ sh, bf16* __restrict__ sl)
{
    int idx = blockIdx.x*256 + threadIdx.x;
    int b = idx >> 14, fg = idx & 16383;
    const float* p = Sp + (size_t)b*NSPLIT_*16384 + fg;
    float s = 0.f;
    #pragma unroll
    for (int t = 0; t < NSPLIT_; ++t) s += p[(size_t)t*16384];
    bf16 h, lo; bsp(s, h, lo);
    sh[idx] = h; sl[idx] = lo;
}

// ---------------------------------------------------------------------------
// HMMA fused: msg = (w1@S - diag.*x)/(N-1); out = lrelu(msg@W5+b5) + x;
// emits next-layer x split (nxh/nxl).
// ---------------------------------------------------------------------------
__global__ void __launch_bounds__(256) k_msg_out(
    const bf16* __restrict__ w1h, const bf16* __restrict__ w1l,
    const float* __restrict__ diag, const float* __restrict__ x,
    const bf16* __restrict__ sh, const bf16* __restrict__ sl,
    const bf16* __restrict__ w5h, const bf16* __restrict__ w5l,
    const float* __restrict__ b5,
    float* __restrict__ out, bf16* __restrict__ nxh, bf16* __restrict__ nxl)
{
    extern __shared__ char sm[];
    __shared__ float ds[128];
    const int tid = threadIdx.x, wid = tid>>5, l = tid&31;
    const int row0 = blockIdx.x * 128, b = blockIdx.x >> 4;
    const int mrow0 = (wid & 3)*32, ncol0 = (wid >> 2)*64;
    const uint32_t sb = smem_u32(sm);

    if (tid < 128) ds[tid] = diag[row0 + tid];

    float acc[2][8][4];
    #pragma unroll
    for (int mt = 0; mt < 2; ++mt)
        #pragma unroll
        for (int n = 0; n < 8; ++n)
            #pragma unroll
            for (int q = 0; q < 4; ++q) acc[mt][n][q] = 0.f;

    for (int c = 0; c < 2; ++c) {
        ldA(sm + G_C0, w1h, row0, c, tid);
        ldA(sm + G_C1, w1l, row0, c, tid);
        ldB(sm + G_C2, sh + (size_t)b*TE_, c, tid);
        ldB(sm + G_C3, sl + (size_t)b*TE_, c, tid);
        __syncthreads();
        #pragma unroll
        for (int kk = 0; kk < 4; ++kk) {
            uint32_t ah[2][4], al_[2][4];
            #pragma unroll
            for (int mt = 0; mt < 2; ++mt) {
                ldsm4(aAddr(sb + G_C0, SA_, mrow0 + mt*16, kk*16, l), ah[mt]);
                ldsm4(aAddr(sb + G_C1, SA_, mrow0 + mt*16, kk*16, l), al_[mt]);
            }
            #pragma unroll
            for (int np = 0; np < 4; ++np) {
                uint32_t bhF[4], blF[4];
                ldsm4t(bAddr(sb + G_C2, SB_, kk*16, ncol0 + np*16, l), bhF);
                ldsm4t(bAddr(sb + G_C3, SB_, kk*16, ncol0 + np*16, l), blF);
                #pragma unroll
                for (int mt = 0; mt < 2; ++mt) {
                    #pragma unroll
                    for (int hnf = 0; hnf < 2; ++hnf) {
                        int n = np*2 + hnf;
                        mma16816(acc[mt][n], ah[mt],  &bhF[hnf*2]);
                        mma16816(acc[mt][n], ah[mt],  &blF[hnf*2]);
                        mma16816(acc[mt][n], al_[mt], &bhF[hnf*2]);
                    }
                }
            }
        }
        __syncthreads();
    }

    {
        bf16* mh = (bf16*)(sm + G_R0);
        bf16* ml = (bf16*)(sm + G_R1);
        #pragma unroll
        for (int mt = 0; mt < 2; ++mt) {
            #pragma unroll
            for (int hf = 0; hf < 2; ++hf) {
                int row = mrow0 + mt*16 + (l >> 2) + hf*8;
                float dv = ds[row];
                size_t gg = (size_t)(row0 + row)*F_;
                #pragma unroll
                for (int n = 0; n < 8; ++n) {
                    int col = ncol0 + n*8 + (l & 3)*2;
                    float2 xv = *(const float2*)&x[gg + col];
                    float a0 = (acc[mt][n][hf*2+0] - dv*xv.x) * INV_NM1_;
                    float a1 = (acc[mt][n][hf*2+1] - dv*xv.y) * INV_NM1_;
                    bf16 h0,l0,h1,l1; bsp(a0,h0,l0); bsp(a1,h1,l1);
                    __nv_bfloat162 p;
                    p.x=h0; p.y=h1; *(__nv_bfloat162*)&mh[row*SB_ + col] = p;
                    p.x=l0; p.y=l1; *(__nv_bfloat162*)&ml[row*SB_ + col] = p;
                }
            }
        }
    }
    __syncthreads();

    #pragma unroll
    for (int mt = 0; mt < 2; ++mt)
        #pragma unroll
        for (int n = 0; n < 8; ++n)
            #pragma unroll
            for (int q = 0; q < 4; ++q) acc[mt][n][q] = 0.f;

    for (int c = 0; c < 2; ++c) {
        ldB(sm + G_C2, w5h, c, tid);
        ldB(sm + G_C3, w5l, c, tid);
        __syncthreads();
        #pragma unroll
        for (int kk = 0; kk < 4; ++kk) {
            uint32_t ah[2][4], al_[2][4];
            #pragma unroll
            for (int mt = 0; mt < 2; ++mt) {
                ldsm4(aAddr(sb + G_R0, SB_, mrow0 + mt*16, c*64 + kk*16, l), ah[mt]);
                ldsm4(aAddr(sb + G_R1, SB_, mrow0 + mt*16, c*64 + kk*16, l), al_[mt]);
            }
            #pragma unroll
            for (int np = 0; np < 4; ++np) {
                uint32_t bhF[4], blF[4];
                ldsm4t(bAddr(sb + G_C2, SB_, kk*16, ncol0 + np*16, l), bhF);
                ldsm4t(bAddr(sb + G_C3, SB_, kk*16, ncol0 + np*16, l), blF);
                #pragma unroll
                for (int mt = 0; mt < 2; ++mt) {
                    #pragma unroll
                    for (int hnf = 0; hnf < 2; ++hnf) {
                        int n = np*2 + hnf;
                        mma16816(acc[mt][n], ah[mt],  &bhF[hnf*2]);
                        mma16816(acc[mt][n], ah[mt],  &blF[hnf*2]);
                        mma16816(acc[mt][n], al_[mt], &bhF[hnf*2]);
                    }
                }
            }
        }
        __syncthreads();
    }

    #pragma unroll
    for (int mt = 0; mt < 2; ++mt) {
        #pragma unroll
        for (int n = 0; n < 8; ++n) {
            int col = ncol0 + n*8 + (l & 3)*2;
            float ba = b5[col], bb = b5[col+1];
            #pragma unroll
            for (int hf = 0; hf < 2; ++hf) {
                int row = mrow0 + mt*16 + (l >> 2) + hf*8;
                size_t gg = (size_t)(row0 + row)*F_ + col;
                float2 xv = *(const float2*)&x[gg];
                float v0 = lrelu(acc[mt][n][hf*2+0] + ba) + xv.x;
                float v1 = lrelu(acc[mt][n][hf*2+1] + bb) + xv.y;
                float2 ov; ov.x = v0; ov.y = v1;
                *(float2*)&out[gg] = ov;
                bf16 h0,l0,h1,l1; bsp(v0,h0,l0); bsp(v1,h1,l1);
                __nv_bfloat162 p;
                p.x=h0; p.y=h1; *(__nv_bfloat162*)&nxh[gg] = p;
                p.x=l0; p.y=l1; *(__nv_bfloat162*)&nxl[gg] = p;
            }
        }
    }
}

// ---------------------------------------------------------------------------
extern "C" void kernel_launch(void* const* d_in, const int* in_sizes, int n_in,
                              void* d_out, int out_size)
{
    const float* x  = (const float*)d_in[0];
    const float* W3 = (const float*)d_in[1];
    const float* b3 = (const float*)d_in[2];
    const float* W4 = (const float*)d_in[3];
    const float* b4 = (const float*)d_in[4];
    const float* W5 = (const float*)d_in[5];
    const float* b5 = (const float*)d_in[6];
    float* out = (float*)d_out;

    cudaFuncSetAttribute(k_w1w2,    cudaFuncAttributeMaxDynamicSharedMemorySize, W_SMEM);
    cudaFuncSetAttribute(k_msg_out, cudaFuncAttributeMaxDynamicSharedMemorySize, G_SMEM);
    cudaFuncSetAttribute(calc_S,    cudaFuncAttributeMaxDynamicSharedMemorySize, S_SMEM);

    float *pdg, *pSp;
    bf16 *pxh, *pxl, *pw1h, *pw1l, *pw2h, *pw2l, *pWh, *pWl, *pSh, *pSl;
    cudaGetSymbolAddress((void**)&pdg,  g_diag);
    cudaGetSymbolAddress((void**)&pSp,  g_Spart);
    cudaGetSymbolAddress((void**)&pxh,  g_xh);
    cudaGetSymbolAddress((void**)&pxl,  g_xl);
    cudaGetSymbolAddress((void**)&pw1h, g_w1h);
    cudaGetSymbolAddress((void**)&pw1l, g_w1l);
    cudaGetSymbolAddress((void**)&pw2h, g_w2h);
    cudaGetSymbolAddress((void**)&pw2l, g_w2l);
    cudaGetSymbolAddress((void**)&pWh,  g_WBh);
    cudaGetSymbolAddress((void**)&pWl,  g_WBl);
    cudaGetSymbolAddress((void**)&pSh,  g_Sh);
    cudaGetSymbolAddress((void**)&pSl,  g_Sl);

    k_splitX<<<(M_*F_/4)/256, 256>>>((const float4*)x, pxh, pxl);
    k_prepW<<<(6*TE_)/256, 256>>>(W3, W4, W5, pWh, pWl);

    for (int l = 0; l < LAYERS_; ++l) {
        const float* xinF = l ? out : x;
        const bf16* Wh = pWh + (size_t)l*3*TE_;
        const bf16* Wl = pWl + (size_t)l*3*TE_;

        k_w1w2<<<M_/128, 256, W_SMEM>>>(pxh, pxl,
                                        Wh, Wl, Wh + TE_, Wl + TE_,
                                        b3 + l*F_, b4 + l*F_,
                                        pw2h, pw2l, pw1h, pw1l, pdg);
        calc_S<<<dim3(NSPLIT_, B_), 256, S_SMEM>>>(pw2h, pw2l, pxh, pxl, pSp);
        k_reduceS<<<(B_*TE_)/256, 256>>>(pSp, pSh, pSl);
        k_msg_out<<<M_/128, 256, G_SMEM>>>(pw1h, pw1l, pdg, xinF,
                                           pSh, pSl,
                                           Wh + 2*TE_, Wl + 2*TE_,
                                           b5 + l*F_, out, pxh, pxl);
    }
}

// round 15
// speedup vs baseline: 1.5732x; 1.0200x over previous
#include <cuda_runtime.h>
#include <cuda_bf16.h>
#include <cstdint>

#define B_ 8
#define N_ 2048
#define F_ 128
#define M_ (B_*N_)
#define LAYERS_ 2
#define NSPLIT_ 16
#define SLOPE_ 0.1f
#define INV_NM1_ (1.0f/2047.0f)
#define TE_ (F_*F_)           // 16384 elems per 128x128 matrix

typedef unsigned long long ull;
typedef __nv_bfloat16 bf16;

// ---------------- scratch (device globals) ----------------
__device__ float g_diag[M_];
__device__ float g_Spart[B_*NSPLIT_*F_*F_];
__device__ __align__(16) bf16 g_xh[M_*F_],  g_xl[M_*F_];
__device__ __align__(16) bf16 g_w1h[M_*F_], g_w1l[M_*F_];
__device__ __align__(16) bf16 g_w2h[M_*F_], g_w2l[M_*F_];
__device__ __align__(16) bf16 g_WBh[LAYERS_*3*TE_], g_WBl[LAYERS_*3*TE_];
__device__ __align__(16) bf16 g_Sh[B_*TE_], g_Sl[B_*TE_];

__device__ __forceinline__ float lrelu(float v){ return v>=0.f? v : SLOPE_*v; }
__device__ __forceinline__ void bsp(float v, bf16&h, bf16&l){
    h = __float2bfloat16(v); l = __float2bfloat16(v - __bfloat162float(h));
}
__device__ __forceinline__ uint32_t smem_u32(const void* p){
    uint32_t a; asm("{ .reg .u64 t; cvta.to.shared.u64 t, %1; cvt.u32.u64 %0, t; }" : "=r"(a) : "l"(p));
    return a;
}

// ---------------- MMA / ldmatrix / cp.async wrappers ----------------
__device__ __forceinline__ void ldsm4(uint32_t addr, uint32_t r[4]){
    asm volatile("ldmatrix.sync.aligned.m8n8.x4.shared.b16 {%0,%1,%2,%3}, [%4];"
        : "=r"(r[0]), "=r"(r[1]), "=r"(r[2]), "=r"(r[3]) : "r"(addr));
}
__device__ __forceinline__ void ldsm4t(uint32_t addr, uint32_t r[4]){
    asm volatile("ldmatrix.sync.aligned.m8n8.x4.trans.shared.b16 {%0,%1,%2,%3}, [%4];"
        : "=r"(r[0]), "=r"(r[1]), "=r"(r[2]), "=r"(r[3]) : "r"(addr));
}
__device__ __forceinline__ void mma16816(float d[4], const uint32_t a[4], const uint32_t b[2]){
    asm volatile("mma.sync.aligned.m16n8k16.row.col.f32.bf16.bf16.f32 "
        "{%0,%1,%2,%3}, {%4,%5,%6,%7}, {%8,%9}, {%0,%1,%2,%3};"
        : "+f"(d[0]), "+f"(d[1]), "+f"(d[2]), "+f"(d[3])
        : "r"(a[0]), "r"(a[1]), "r"(a[2]), "r"(a[3]), "r"(b[0]), "r"(b[1]));
}
__device__ __forceinline__ void cpa16(uint32_t dst, const void* src){
    asm volatile("cp.async.cg.shared.global [%0], [%1], 16;" :: "r"(dst), "l"(src));
}
#define CP_COMMIT() asm volatile("cp.async.commit_group;" ::: "memory")
#define CP_WAIT(n)  asm volatile("cp.async.wait_group %0;" :: "n"(n) : "memory")

// smem strides (bf16 elems)
#define SA_ 72      // 144 B (16B-aligned)
#define SB_ 136     // 272 B (16B-aligned)
#define ATB_ 18432  // 128 x SA_ x 2 bytes (A tile)
#define BTB_ 17408  // 64 x SB_ x 2 bytes (B tile)
// k_w1w2: per-chunk block [AH][AL][B3H][B3L][B4H][B4L]
#define W_BLK (2*ATB_ + 4*BTB_)          // 106496
#define W_SMEM (2*W_BLK)                 // 212992
// calc_S: per-chunk block [AH][AL][BH][BL] (all B-style)
#define S_BLK (4*BTB_)                   // 69632
#define S_SMEM (2*S_BLK)                 // 139264
// k_msg_out: [R0 34816][R1 34816] + 2 chunk blocks [AH][AL][BH][BL]
#define G_RSZ 34816
#define G_BLK (2*ATB_ + 2*BTB_)          // 71680
#define G_CH0 (2*G_RSZ)                  // 69632
#define G_SMEM (2*G_RSZ + 2*G_BLK)       // 212992

// ---------------------------------------------------------------------------
// async chunk loaders
__device__ __forceinline__ void ldA_a(uint32_t sdst, const bf16* g, int row0, int c, int tid){
    #pragma unroll
    for (int i = 0; i < 4; ++i) {
        int f4 = tid + i*256;
        int r = f4 >> 3, q = (f4 & 7)*8;
        cpa16(sdst + (uint32_t)(r*SA_ + q)*2, &g[(size_t)(row0 + r)*F_ + c*64 + q]);
    }
}
__device__ __forceinline__ void ldB_a(uint32_t sdst, const bf16* g, int c, int tid){
    #pragma unroll
    for (int i = 0; i < 4; ++i) {
        int f4 = tid + i*256;
        int r = f4 >> 4, q = (f4 & 15)*8;
        cpa16(sdst + (uint32_t)(r*SB_ + q)*2, &g[(size_t)(c*64 + r)*F_ + q]);
    }
}

// fragment address helpers (lane-dependent); strides in bf16 elems
__device__ __forceinline__ uint32_t aAddr(uint32_t base, int stride, int row16, int kcol, int l){
    int row = row16 + (l & 7) + ((l >> 3) & 1)*8;
    int kc  = kcol + ((l >> 4) & 1)*8;
    return base + (uint32_t)(row*stride + kc)*2;
}
__device__ __forceinline__ uint32_t bAddr(uint32_t base, int stride, int krow, int ncol, int l){
    int kr = krow + (l & 7) + ((l >> 3) & 1)*8;
    int nc = ncol + ((l >> 4) & 1)*8;
    return base + (uint32_t)(kr*stride + nc)*2;
}
// trans-load of [k][f]-stored tile as A-operand (inverse half-pairing of bAddr)
__device__ __forceinline__ uint32_t atAddr(uint32_t base, int stride, int krow, int fcol, int l){
    int kr = krow + (l & 7) + ((l >> 4) & 1)*8;
    int fc = fcol + ((l >> 3) & 1)*8;
    return base + (uint32_t)(kr*stride + fc)*2;
}

// ---------------------------------------------------------------------------
// prep kernels
__global__ void __launch_bounds__(256) k_splitX(const float4* __restrict__ X,
    bf16* __restrict__ xh, bf16* __restrict__ xl)
{
    int idx = blockIdx.x*256 + threadIdx.x;
    float4 v = X[idx];
    bf16 h[4], l[4];
    bsp(v.x,h[0],l[0]); bsp(v.y,h[1],l[1]); bsp(v.z,h[2],l[2]); bsp(v.w,h[3],l[3]);
    __nv_bfloat162 p0, p1;
    p0.x=h[0]; p0.y=h[1]; p1.x=h[2]; p1.y=h[3];
    uint2 u; u.x = *(uint32_t*)&p0; u.y = *(uint32_t*)&p1;
    *(uint2*)&xh[idx*4] = u;
    p0.x=l[0]; p0.y=l[1]; p1.x=l[2]; p1.y=l[3];
    u.x = *(uint32_t*)&p0; u.y = *(uint32_t*)&p1;
    *(uint2*)&xl[idx*4] = u;
}

__global__ void __launch_bounds__(256) k_prepW(
    const float* __restrict__ W3, const float* __restrict__ W4, const float* __restrict__ W5,
    bf16* __restrict__ wh, bf16* __restrict__ wl)
{
    int idx = blockIdx.x*256 + threadIdx.x;
    int m = idx >> 14, e = idx & 16383;
    int l = m / 3, w = m % 3;
    const float* W = (w==0 ? W3 : (w==1 ? W4 : W5)) + (size_t)l*TE_;
    bf16 h, lo; bsp(W[e], h, lo);
    wh[(size_t)m*TE_ + e] = h; wl[(size_t)m*TE_ + e] = lo;
}

// ---------------------------------------------------------------------------
// HMMA fused w1/w2/diag, double-buffered cp.async pipeline.
// ---------------------------------------------------------------------------
__global__ void __launch_bounds__(256) k_w1w2(
    const bf16* __restrict__ xh, const bf16* __restrict__ xl,
    const bf16* __restrict__ w3h, const bf16* __restrict__ w3l,
    const bf16* __restrict__ w4h, const bf16* __restrict__ w4l,
    const float* __restrict__ b3, const float* __restrict__ b4,
    bf16* __restrict__ w2h, bf16* __restrict__ w2l,
    bf16* __restrict__ w1h, bf16* __restrict__ w1l,
    float* __restrict__ diag)
{
    extern __shared__ char sm[];
    __shared__ float dsh[256];
    const int tid = threadIdx.x, wid = tid>>5, l = tid&31;
    const int row0 = blockIdx.x * 128;
    const int mrow0 = (wid & 3)*32, ncol0 = (wid >> 2)*64;
    const uint32_t sb = smem_u32(sm);

    // prefetch both chunks (one commit group each)
    #pragma unroll
    for (int c = 0; c < 2; ++c) {
        uint32_t base = sb + c*W_BLK;
        ldA_a(base,            xh,  row0, c, tid);
        ldA_a(base + ATB_,     xl,  row0, c, tid);
        ldB_a(base + 2*ATB_,           w3h, c, tid);
        ldB_a(base + 2*ATB_ + BTB_,    w3l, c, tid);
        ldB_a(base + 2*ATB_ + 2*BTB_,  w4h, c, tid);
        ldB_a(base + 2*ATB_ + 3*BTB_,  w4l, c, tid);
        CP_COMMIT();
    }

    float acc3[2][8][4], acc4[2][8][4];
    #pragma unroll
    for (int mt = 0; mt < 2; ++mt)
        #pragma unroll
        for (int n = 0; n < 8; ++n)
            #pragma unroll
            for (int q = 0; q < 4; ++q) { acc3[mt][n][q] = 0.f; acc4[mt][n][q] = 0.f; }

    #pragma unroll
    for (int c = 0; c < 2; ++c) {
        if (c == 0) CP_WAIT(1); else CP_WAIT(0);
        __syncthreads();
        uint32_t base = sb + c*W_BLK;
        uint32_t AH = base, AL = base + ATB_;
        uint32_t B3H = base + 2*ATB_, B3L = B3H + BTB_, B4H = B3L + BTB_, B4L = B4H + BTB_;
        #pragma unroll
        for (int kk = 0; kk < 4; ++kk) {
            uint32_t ah[2][4], al_[2][4];
            #pragma unroll
            for (int mt = 0; mt < 2; ++mt) {
                ldsm4(aAddr(AH, SA_, mrow0 + mt*16, kk*16, l), ah[mt]);
                ldsm4(aAddr(AL, SA_, mrow0 + mt*16, kk*16, l), al_[mt]);
            }
            #pragma unroll
            for (int np = 0; np < 4; ++np) {
                uint32_t b3hF[4], b3lF[4], b4hF[4], b4lF[4];
                ldsm4t(bAddr(B3H, SB_, kk*16, ncol0 + np*16, l), b3hF);
                ldsm4t(bAddr(B3L, SB_, kk*16, ncol0 + np*16, l), b3lF);
                ldsm4t(bAddr(B4H, SB_, kk*16, ncol0 + np*16, l), b4hF);
                ldsm4t(bAddr(B4L, SB_, kk*16, ncol0 + np*16, l), b4lF);
                #pragma unroll
                for (int mt = 0; mt < 2; ++mt) {
                    #pragma unroll
                    for (int hnf = 0; hnf < 2; ++hnf) {
                        int n = np*2 + hnf;
                        mma16816(acc3[mt][n], ah[mt],  &b3hF[hnf*2]);
                        mma16816(acc3[mt][n], ah[mt],  &b3lF[hnf*2]);
                        mma16816(acc3[mt][n], al_[mt], &b3hF[hnf*2]);
                        mma16816(acc4[mt][n], ah[mt],  &b4hF[hnf*2]);
                        mma16816(acc4[mt][n], ah[mt],  &b4lF[hnf*2]);
                        mma16816(acc4[mt][n], al_[mt], &b4hF[hnf*2]);
                    }
                }
            }
        }
    }

    float dp[2][2] = {{0.f,0.f},{0.f,0.f}};
    #pragma unroll
    for (int mt = 0; mt < 2; ++mt) {
        #pragma unroll
        for (int n = 0; n < 8; ++n) {
            int col = ncol0 + n*8 + (l & 3)*2;
            float bb3a = b3[col], bb3b = b3[col+1];
            float bb4a = b4[col], bb4b = b4[col+1];
            #pragma unroll
            for (int hf = 0; hf < 2; ++hf) {
                int row = mrow0 + mt*16 + (l >> 2) + hf*8;
                float v1a = lrelu(acc3[mt][n][hf*2+0] + bb3a);
                float v1b = lrelu(acc3[mt][n][hf*2+1] + bb3b);
                float v2a = lrelu(acc4[mt][n][hf*2+0] + bb4a);
                float v2b = lrelu(acc4[mt][n][hf*2+1] + bb4b);
                dp[mt][hf] += v1a*v2a + v1b*v2b;
                size_t gg = (size_t)(row0 + row)*F_ + col;
                bf16 h0,l0,h1,l1;
                bsp(v1a,h0,l0); bsp(v1b,h1,l1);
                __nv_bfloat162 p;
                p.x=h0; p.y=h1; *(__nv_bfloat162*)&w1h[gg] = p;
                p.x=l0; p.y=l1; *(__nv_bfloat162*)&w1l[gg] = p;
                bsp(v2a,h0,l0); bsp(v2b,h1,l1);
                p.x=h0; p.y=h1; *(__nv_bfloat162*)&w2h[gg] = p;
                p.x=l0; p.y=l1; *(__nv_bfloat162*)&w2l[gg] = p;
            }
        }
    }
    #pragma unroll
    for (int mt = 0; mt < 2; ++mt)
        #pragma unroll
        for (int hf = 0; hf < 2; ++hf) {
            float d = dp[mt][hf];
            d += __shfl_xor_sync(0xffffffffu, d, 1);
            d += __shfl_xor_sync(0xffffffffu, d, 2);
            if ((l & 3) == 0) {
                int row = mrow0 + mt*16 + (l >> 2) + hf*8;
                dsh[(wid >> 2)*128 + row] = d;
            }
        }
    __syncthreads();
    if (tid < 128) diag[row0 + tid] = dsh[tid] + dsh[128 + tid];
}

// ---------------------------------------------------------------------------
// HMMA calc_S, double-buffered: partial S[b] = w2_chunk^T @ x_chunk.
// ---------------------------------------------------------------------------
__global__ void __launch_bounds__(256) calc_S(
    const bf16* __restrict__ w2h, const bf16* __restrict__ w2l,
    const bf16* __restrict__ xh,  const bf16* __restrict__ xl,
    float* __restrict__ Spart)
{
    extern __shared__ char sm[];
    const int tid = threadIdx.x, wid = tid>>5, l = tid&31;
    const int split = blockIdx.x, b = blockIdx.y;
    const size_t k0F = (size_t)(b*N_ + split*128)*F_;
    const int mrow0 = (wid & 3)*32, ncol0 = (wid >> 2)*64;
    const uint32_t sb = smem_u32(sm);

    #pragma unroll
    for (int c = 0; c < 2; ++c) {
        uint32_t base = sb + c*S_BLK;
        ldB_a(base,          w2h + k0F, c, tid);
        ldB_a(base + BTB_,   w2l + k0F, c, tid);
        ldB_a(base + 2*BTB_, xh + k0F, c, tid);
        ldB_a(base + 3*BTB_, xl + k0F, c, tid);
        CP_COMMIT();
    }

    float acc[2][8][4];
    #pragma unroll
    for (int mt = 0; mt < 2; ++mt)
        #pragma unroll
        for (int n = 0; n < 8; ++n)
            #pragma unroll
            for (int q = 0; q < 4; ++q) acc[mt][n][q] = 0.f;

    #pragma unroll
    for (int c = 0; c < 2; ++c) {
        if (c == 0) CP_WAIT(1); else CP_WAIT(0);
        __syncthreads();
        uint32_t AH = sb + c*S_BLK, AL = AH + BTB_, BH = AL + BTB_, BL = BH + BTB_;
        #pragma unroll
        for (int kk = 0; kk < 4; ++kk) {
            uint32_t ah[2][4], al_[2][4];
            #pragma unroll
            for (int mt = 0; mt < 2; ++mt) {
                ldsm4t(atAddr(AH, SB_, kk*16, mrow0 + mt*16, l), ah[mt]);
                ldsm4t(atAddr(AL, SB_, kk*16, mrow0 + mt*16, l), al_[mt]);
            }
            #pragma unroll
            for (int np = 0; np < 4; ++np) {
                uint32_t bhF[4], blF[4];
                ldsm4t(bAddr(BH, SB_, kk*16, ncol0 + np*16, l), bhF);
                ldsm4t(bAddr(BL, SB_, kk*16, ncol0 + np*16, l), blF);
                #pragma unroll
                for (int mt = 0; mt < 2; ++mt) {
                    #pragma unroll
                    for (int hnf = 0; hnf < 2; ++hnf) {
                        int n = np*2 + hnf;
                        mma16816(acc[mt][n], ah[mt],  &bhF[hnf*2]);
                        mma16816(acc[mt][n], ah[mt],  &blF[hnf*2]);
                        mma16816(acc[mt][n], al_[mt], &bhF[hnf*2]);
                    }
                }
            }
        }
    }

    float* out = Spart + ((size_t)b*NSPLIT_ + split)*TE_;
    #pragma unroll
    for (int mt = 0; mt < 2; ++mt) {
        #pragma unroll
        for (int n = 0; n < 8; ++n) {
            int col = ncol0 + n*8 + (l & 3)*2;
            #pragma unroll
            for (int hf = 0; hf < 2; ++hf) {
                int row = mrow0 + mt*16 + (l >> 2) + hf*8;
                float2 v; v.x = acc[mt][n][hf*2+0]; v.y = acc[mt][n][hf*2+1];
                *(float2*)&out[(size_t)row*F_ + col] = v;
            }
        }
    }
}

// reduce split-K partials -> S bf16 hi/lo
__global__ void __launch_bounds__(256) k_reduceS(
    const float* __restrict__ Sp, bf16* __restrict__ sh, bf16* __restrict__ sl)
{
    int idx = blockIdx.x*256 + threadIdx.x;
    int b = idx >> 14, fg = idx & 16383;
    const float* p = Sp + (size_t)b*NSPLIT_*16384 + fg;
    float s = 0.f;
    #pragma unroll
    for (int t = 0; t < NSPLIT_; ++t) s += p[(size_t)t*16384];
    bf16 h, lo; bsp(s, h, lo);
    sh[idx] = h; sl[idx] = lo;
}

// ---------------------------------------------------------------------------
// HMMA fused msg+out, double-buffered; W5 loads overlap the msg epilogue.
// ---------------------------------------------------------------------------
__global__ void __launch_bounds__(256) k_msg_out(
    const bf16* __restrict__ w1h, const bf16* __restrict__ w1l,
    const float* __restrict__ diag, const float* __restrict__ x,
    const bf16* __restrict__ sh, const bf16* __restrict__ sl,
    const bf16* __restrict__ w5h, const bf16* __restrict__ w5l,
    const float* __restrict__ b5,
    float* __restrict__ out, bf16* __restrict__ nxh, bf16* __restrict__ nxl)
{
    extern __shared__ char sm[];
    __shared__ float ds[128];
    const int tid = threadIdx.x, wid = tid>>5, l = tid&31;
    const int row0 = blockIdx.x * 128, b = blockIdx.x >> 4;
    const int mrow0 = (wid & 3)*32, ncol0 = (wid >> 2)*64;
    const uint32_t sb = smem_u32(sm);

    // prefetch stage-1 chunks
    #pragma unroll
    for (int c = 0; c < 2; ++c) {
        uint32_t base = sb + G_CH0 + c*G_BLK;
        ldA_a(base,          w1h, row0, c, tid);
        ldA_a(base + ATB_,   w1l, row0, c, tid);
        ldB_a(base + 2*ATB_,        sh + (size_t)b*TE_, c, tid);
        ldB_a(base + 2*ATB_ + BTB_, sl + (size_t)b*TE_, c, tid);
        CP_COMMIT();
    }
    if (tid < 128) ds[tid] = diag[row0 + tid];

    float acc[2][8][4];
    #pragma unroll
    for (int mt = 0; mt < 2; ++mt)
        #pragma unroll
        for (int n = 0; n < 8; ++n)
            #pragma unroll
            for (int q = 0; q < 4; ++q) acc[mt][n][q] = 0.f;

    // ---- stage 1: acc = w1 @ S ----
    #pragma unroll
    for (int c = 0; c < 2; ++c) {
        if (c == 0) CP_WAIT(1); else CP_WAIT(0);
        __syncthreads();
        uint32_t base = sb + G_CH0 + c*G_BLK;
        uint32_t AH = base, AL = base + ATB_, BH = base + 2*ATB_, BL = BH + BTB_;
        #pragma unroll
        for (int kk = 0; kk < 4; ++kk) {
            uint32_t ah[2][4], al_[2][4];
            #pragma unroll
            for (int mt = 0; mt < 2; ++mt) {
                ldsm4(aAddr(AH, SA_, mrow0 + mt*16, kk*16, l), ah[mt]);
                ldsm4(aAddr(AL, SA_, mrow0 + mt*16, kk*16, l), al_[mt]);
            }
            #pragma unroll
            for (int np = 0; np < 4; ++np) {
                uint32_t bhF[4], blF[4];
                ldsm4t(bAddr(BH, SB_, kk*16, ncol0 + np*16, l), bhF);
                ldsm4t(bAddr(BL, SB_, kk*16, ncol0 + np*16, l), blF);
                #pragma unroll
                for (int mt = 0; mt < 2; ++mt) {
                    #pragma unroll
                    for (int hnf = 0; hnf < 2; ++hnf) {
                        int n = np*2 + hnf;
                        mma16816(acc[mt][n], ah[mt],  &bhF[hnf*2]);
                        mma16816(acc[mt][n], ah[mt],  &blF[hnf*2]);
                        mma16816(acc[mt][n], al_[mt], &bhF[hnf*2]);
                    }
                }
            }
        }
    }
    __syncthreads();   // all reads of chunk buffers done before W5 overwrites

    // issue W5 loads into the B slots of both chunk buffers (overlaps msg epilogue)
    #pragma unroll
    for (int c = 0; c < 2; ++c) {
        uint32_t base = sb + G_CH0 + c*G_BLK;
        ldB_a(base + 2*ATB_,        w5h, c, tid);
        ldB_a(base + 2*ATB_ + BTB_, w5l, c, tid);
        CP_COMMIT();
    }

    // msg epilogue: (acc - diag*x)/(N-1) -> bf16 h/l into R0/R1
    {
        bf16* mh = (bf16*)(sm);
        bf16* ml = (bf16*)(sm + G_RSZ);
        #pragma unroll
        for (int mt = 0; mt < 2; ++mt) {
            #pragma unroll
            for (int hf = 0; hf < 2; ++hf) {
                int row = mrow0 + mt*16 + (l >> 2) + hf*8;
                float dv = ds[row];
                size_t gg = (size_t)(row0 + row)*F_;
                #pragma unroll
                for (int n = 0; n < 8; ++n) {
                    int col = ncol0 + n*8 + (l & 3)*2;
                    float2 xv = *(const float2*)&x[gg + col];
                    float a0 = (acc[mt][n][hf*2+0] - dv*xv.x) * INV_NM1_;
                    float a1 = (acc[mt][n][hf*2+1] - dv*xv.y) * INV_NM1_;
                    bf16 h0,l0,h1,l1; bsp(a0,h0,l0); bsp(a1,h1,l1);
                    __nv_bfloat162 p;
                    p.x=h0; p.y=h1; *(__nv_bfloat162*)&mh[row*SB_ + col] = p;
                    p.x=l0; p.y=l1; *(__nv_bfloat162*)&ml[row*SB_ + col] = p;
                }
            }
        }
    }
    CP_WAIT(0);
    __syncthreads();

    // ---- stage 2: acc = msg @ W5 ----
    #pragma unroll
    for (int mt = 0; mt < 2; ++mt)
        #pragma unroll
        for (int n = 0; n < 8; ++n)
            #pragma unroll
            for (int q = 0; q < 4; ++q) acc[mt][n][q] = 0.f;

    #pragma unroll
    for (int c = 0; c < 2; ++c) {
        uint32_t base = sb + G_CH0 + c*G_BLK;
        uint32_t BH = base + 2*ATB_, BL = BH + BTB_;
        #pragma unroll
        for (int kk = 0; kk < 4; ++kk) {
            uint32_t ah[2][4], al_[2][4];
            #pragma unroll
            for (int mt = 0; mt < 2; ++mt) {
                ldsm4(aAddr(sb,         SB_, mrow0 + mt*16, c*64 + kk*16, l), ah[mt]);
                ldsm4(aAddr(sb + G_RSZ, SB_, mrow0 + mt*16, c*64 + kk*16, l), al_[mt]);
            }
            #pragma unroll
            for (int np = 0; np < 4; ++np) {
                uint32_t bhF[4], blF[4];
                ldsm4t(bAddr(BH, SB_, kk*16, ncol0 + np*16, l), bhF);
                ldsm4t(bAddr(BL, SB_, kk*16, ncol0 + np*16, l), blF);
                #pragma unroll
                for (int mt = 0; mt < 2; ++mt) {
                    #pragma unroll
                    for (int hnf = 0; hnf < 2; ++hnf) {
                        int n = np*2 + hnf;
                        mma16816(acc[mt][n], ah[mt],  &bhF[hnf*2]);
                        mma16816(acc[mt][n], ah[mt],  &blF[hnf*2]);
                        mma16816(acc[mt][n], al_[mt], &bhF[hnf*2]);
                    }
                }
            }
        }
    }

    // final epilogue
    #pragma unroll
    for (int mt = 0; mt < 2; ++mt) {
        #pragma unroll
        for (int n = 0; n < 8; ++n) {
            int col = ncol0 + n*8 + (l & 3)*2;
            float ba = b5[col], bb = b5[col+1];
            #pragma unroll
            for (int hf = 0; hf < 2; ++hf) {
                int row = mrow0 + mt*16 + (l >> 2) + hf*8;
                size_t gg = (size_t)(row0 + row)*F_ + col;
                float2 xv = *(const float2*)&x[gg];
                float v0 = lrelu(acc[mt][n][hf*2+0] + ba) + xv.x;
                float v1 = lrelu(acc[mt][n][hf*2+1] + bb) + xv.y;
                float2 ov; ov.x = v0; ov.y = v1;
                *(float2*)&out[gg] = ov;
                bf16 h0,l0,h1,l1; bsp(v0,h0,l0); bsp(v1,h1,l1);
                __nv_bfloat162 p;
                p.x=h0; p.y=h1; *(__nv_bfloat162*)&nxh[gg] = p;
                p.x=l0; p.y=l1; *(__nv_bfloat162*)&nxl[gg] = p;
            }
        }
    }
}

// ---------------------------------------------------------------------------
extern "C" void kernel_launch(void* const* d_in, const int* in_sizes, int n_in,
                              void* d_out, int out_size)
{
    const float* x  = (const float*)d_in[0];
    const float* W3 = (const float*)d_in[1];
    const float* b3 = (const float*)d_in[2];
    const float* W4 = (const float*)d_in[3];
    const float* b4 = (const float*)d_in[4];
    const float* W5 = (const float*)d_in[5];
    const float* b5 = (const float*)d_in[6];
    float* out = (float*)d_out;

    cudaFuncSetAttribute(k_w1w2,    cudaFuncAttributeMaxDynamicSharedMemorySize, W_SMEM);
    cudaFuncSetAttribute(k_msg_out, cudaFuncAttributeMaxDynamicSharedMemorySize, G_SMEM);
    cudaFuncSetAttribute(calc_S,    cudaFuncAttributeMaxDynamicSharedMemorySize, S_SMEM);

    float *pdg, *pSp;
    bf16 *pxh, *pxl, *pw1h, *pw1l, *pw2h, *pw2l, *pWh, *pWl, *pSh, *pSl;
    cudaGetSymbolAddress((void**)&pdg,  g_diag);
    cudaGetSymbolAddress((void**)&pSp,  g_Spart);
    cudaGetSymbolAddress((void**)&pxh,  g_xh);
    cudaGetSymbolAddress((void**)&pxl,  g_xl);
    cudaGetSymbolAddress((void**)&pw1h, g_w1h);
    cudaGetSymbolAddress((void**)&pw1l, g_w1l);
    cudaGetSymbolAddress((void**)&pw2h, g_w2h);
    cudaGetSymbolAddress((void**)&pw2l, g_w2l);
    cudaGetSymbolAddress((void**)&pWh,  g_WBh);
    cudaGetSymbolAddress((void**)&pWl,  g_WBl);
    cudaGetSymbolAddress((void**)&pSh,  g_Sh);
    cudaGetSymbolAddress((void**)&pSl,  g_Sl);

    k_splitX<<<(M_*F_/4)/256, 256>>>((const float4*)x, pxh, pxl);
    k_prepW<<<(6*TE_)/256, 256>>>(W3, W4, W5, pWh, pWl);

    for (int l = 0; l < LAYERS_; ++l) {
        const float* xinF = l ? out : x;
        const bf16* Wh = pWh + (size_t)l*3*TE_;
        const bf16* Wl = pWl + (size_t)l*3*TE_;

        k_w1w2<<<M_/128, 256, W_SMEM>>>(pxh, pxl,
                                        Wh, Wl, Wh + TE_, Wl + TE_,
                                        b3 + l*F_, b4 + l*F_,
                                        pw2h, pw2l, pw1h, pw1l, pdg);
        calc_S<<<dim3(NSPLIT_, B_), 256, S_SMEM>>>(pw2h, pw2l, pxh, pxl, pSp);
        k_reduceS<<<(B_*TE_)/256, 256>>>(pSp, pSh, pSl);
        k_msg_out<<<M_/128, 256, G_SMEM>>>(pw1h, pw1l, pdg, xinF,
                                           pSh, pSl,
                                           Wh + 2*TE_, Wl + 2*TE_,
                                           b5 + l*F_, out, pxh, pxl);
    }
}